// round 13
// baseline (speedup 1.0000x reference)
#include <cuda_runtime.h>
#include <cuda_bf16.h>
#include <cuda_fp16.h>
#include <math.h>
#include <stdint.h>

#define BATCH 8
#define CH    256
#define NPIX  4096
#define QKVC  768
#define GROUPS 8
#define CPG    32
#define EPS    1e-5f
#define QK_FOLD 0.0901687145f

// ---------------- scratch ----------------
__device__ __align__(16) unsigned short g_xh[BATCH * NPIX * CH];  // bf16 x^T [b][n][c]
__device__ __align__(16) unsigned short g_q[BATCH * NPIX * CH];   // bf16 [b][n][c], q*QK_FOLD
__device__ __align__(16) unsigned short g_k[BATCH * NPIX * CH];   // bf16 [b][n][c]
__device__ __align__(16) unsigned short g_v[BATCH * CH * NPIX];   // fp16 [b][c][n]
__device__ __align__(16) unsigned short g_attnh[BATCH * NPIX * CH]; // bf16 [b][n][c]
__device__ __align__(16) unsigned short g_wbh[BATCH * QKVC * CH]; // bf16 folded qkv weights
__device__ __align__(16) unsigned short g_wph[CH * CH];           // bf16 w_proj [o][c]
__device__ float g_bb  [BATCH * QKVC];
__device__ float g_part[BATCH * GROUPS * 8];

// ================= helpers =================
__device__ __forceinline__ uint32_t smem_u32(const void* p) {
    uint32_t a;
    asm("{ .reg .u64 t; cvta.to.shared.u64 t, %1; cvt.u32.u64 %0, t; }" : "=r"(a) : "l"(p));
    return a;
}
__device__ __forceinline__ float ex2f(float x) {
    float r; asm("ex2.approx.f32 %0, %1;" : "=f"(r) : "f"(x)); return r;
}
__device__ __forceinline__ void ldsm4(uint32_t& r0, uint32_t& r1, uint32_t& r2, uint32_t& r3,
                                      uint32_t addr) {
    asm volatile("ldmatrix.sync.aligned.m8n8.x4.shared.b16 {%0,%1,%2,%3}, [%4];"
                 : "=r"(r0), "=r"(r1), "=r"(r2), "=r"(r3) : "r"(addr));
}
__device__ __forceinline__ void mma_bf16(float* d, uint32_t a0, uint32_t a1, uint32_t a2,
                                         uint32_t a3, uint32_t b0, uint32_t b1) {
    asm volatile("mma.sync.aligned.m16n8k16.row.col.f32.bf16.bf16.f32 "
                 "{%0,%1,%2,%3}, {%4,%5,%6,%7}, {%8,%9}, {%0,%1,%2,%3};"
                 : "+f"(d[0]), "+f"(d[1]), "+f"(d[2]), "+f"(d[3])
                 : "r"(a0), "r"(a1), "r"(a2), "r"(a3), "r"(b0), "r"(b1));
}
__device__ __forceinline__ void mma_f16acc(uint32_t* d, uint32_t a0, uint32_t a1, uint32_t a2,
                                           uint32_t a3, uint32_t b0, uint32_t b1) {
    asm volatile("mma.sync.aligned.m16n8k16.row.col.f16.f16.f16.f16 "
                 "{%0,%1}, {%2,%3,%4,%5}, {%6,%7}, {%0,%1};"
                 : "+r"(d[0]), "+r"(d[1])
                 : "r"(a0), "r"(a1), "r"(a2), "r"(a3), "r"(b0), "r"(b1));
}
#define CP_ASYNC(dst, src) \
    asm volatile("cp.async.cg.shared.global [%0], [%1], 16;" :: "r"(dst), "l"(src))
#define CP_COMMIT() asm volatile("cp.async.commit_group;" ::: "memory")
#define CP_WAIT0()  asm volatile("cp.async.wait_group 0;" ::: "memory")

// ---------------- K0: groupnorm partial sums ----------------
__global__ void gn_part_kernel(const float* __restrict__ x) {
    int id = blockIdx.x;
    int b = id >> 5, g = (id >> 2) & 7, qtr = id & 3;
    const float4* xv = (const float4*)(x + ((size_t)b * CH + g * CPG) * NPIX) + qtr * 8192;
    float s = 0.f, s2 = 0.f;
    for (int i = threadIdx.x; i < 8192; i += 256) {
        float4 v = xv[i];
        s  += v.x + v.y + v.z + v.w;
        s2 += v.x*v.x + v.y*v.y + v.z*v.z + v.w*v.w;
    }
    __shared__ float rs[256], rs2[256];
    rs[threadIdx.x] = s; rs2[threadIdx.x] = s2;
    __syncthreads();
    for (int o = 128; o > 0; o >>= 1) {
        if (threadIdx.x < o) { rs[threadIdx.x] += rs[threadIdx.x+o]; rs2[threadIdx.x] += rs2[threadIdx.x+o]; }
        __syncthreads();
    }
    if (threadIdx.x == 0) {
        g_part[(b * 8 + g) * 8 + qtr * 2]     = rs[0];
        g_part[(b * 8 + g) * 8 + qtr * 2 + 1] = rs2[0];
    }
}

// ---------------- K0b: transpose x -> bf16 [b][n][c] ----------------
__global__ void xpose_kernel(const float* __restrict__ x) {
    __shared__ float ts[32][65];
    int b = blockIdx.z, c0 = blockIdx.y * 32, n0 = blockIdx.x * 64;
    const float* xb = x + ((size_t)b * CH + c0) * NPIX + n0;
    int tid = threadIdx.x;
    #pragma unroll
    for (int it = 0; it < 2; ++it) {
        int p = it * 256 + tid;
        int r = p >> 4, q = p & 15;
        float4 v = *(const float4*)(xb + (size_t)r * NPIX + q * 4);
        ts[r][q*4+0] = v.x; ts[r][q*4+1] = v.y; ts[r][q*4+2] = v.z; ts[r][q*4+3] = v.w;
    }
    __syncthreads();
    int nr = tid >> 2, cq = tid & 3;
    union { __nv_bfloat162 h[4]; uint4 u; } pk;
    #pragma unroll
    for (int j = 0; j < 4; ++j)
        pk.h[j] = __floats2bfloat162_rn(ts[cq*8 + 2*j][nr], ts[cq*8 + 2*j + 1][nr]);
    *(uint4*)(g_xh + ((size_t)b * NPIX + n0 + nr) * CH + c0 + cq * 8) = pk.u;
}

// ---------------- K1: stats finalize + fold affine into qkv weights ----------------
__global__ void build_wb_kernel(const float* __restrict__ w_qkv,
                                const float* __restrict__ b_qkv,
                                const float* __restrict__ gamma,
                                const float* __restrict__ beta) {
    int o = blockIdx.x, b = blockIdx.y, c = threadIdx.x;
    int g = c >> 5;
    const float* pp = g_part + (b * 8 + g) * 8;
    float s  = (pp[0] + pp[2]) + (pp[4] + pp[6]);
    float s2 = (pp[1] + pp[3]) + (pp[5] + pp[7]);
    float mean = s  * (1.0f / 131072.0f);
    float var  = s2 * (1.0f / 131072.0f) - mean * mean;
    float rinv = rsqrtf(var + EPS);
    float sc = rinv * gamma[c];
    float tt = beta[c] - mean * sc;
    float w = w_qkv[o * CH + c];
    __nv_bfloat16 wh = __float2bfloat16(w * sc);
    g_wbh[((size_t)b * QKVC + o) * CH + c] = *(unsigned short*)&wh;
    __shared__ float red[256];
    red[c] = w * tt;
    __syncthreads();
    for (int off = 128; off > 0; off >>= 1) {
        if (c < off) red[c] += red[c + off];
        __syncthreads();
    }
    if (c == 0) g_bb[b * QKVC + o] = b_qkv[o] + red[0];
}

// ---------------- K1b: w_proj -> bf16 ----------------
__global__ void wconv_kernel(const float* __restrict__ w_proj) {
    int i = blockIdx.x * 256 + threadIdx.x;
    float4 v = ((const float4*)w_proj)[i];
    union { __nv_bfloat162 h[2]; uint2 u; } pk;
    pk.h[0] = __floats2bfloat162_rn(v.x, v.y);
    pk.h[1] = __floats2bfloat162_rn(v.z, v.w);
    ((uint2*)g_wph)[i] = pk.u;
}

// ---------------- K2: QKV GEMM (bf16 mma) ----------------
#define GB_SMEM 65536

__device__ __forceinline__ void gemm_issue(uint32_t sb, const unsigned short* Abase,
                                           const unsigned short* Bbase, int s, int tid) {
    int buf = s & 1, c0 = s * 64;
    uint32_t adst = sb + buf * 16384;
    uint32_t bdst = sb + 32768 + buf * 16384;
    #pragma unroll
    for (int it = 0; it < 4; ++it) {
        int t = it * 256 + tid;
        int r = t >> 3, ch = t & 7;
        CP_ASYNC(adst + r*128 + ((ch ^ (r & 7)) << 4), Abase + (size_t)r * CH + c0 + ch * 8);
    }
    #pragma unroll
    for (int it = 0; it < 4; ++it) {
        int t = it * 256 + tid;
        int r = t >> 3, ch = t & 7;
        CP_ASYNC(bdst + r*128 + ((ch ^ (r & 7)) << 4), Bbase + (size_t)r * CH + c0 + ch * 8);
    }
}

__device__ __forceinline__ void gemm_bf16_core(uint32_t sb, const unsigned short* Abase,
                                               const unsigned short* Bbase,
                                               float acc[4][4][4], int tid) {
    int l = tid & 31, w = tid >> 5;
    int wm = w & 1, wn = w >> 1;
    int a_lrow = l & 15, a_lch = l >> 4;
    int b_roff = (l & 7) + ((l & 16) >> 1);
    int b_choff = (l >> 3) & 1;

    gemm_issue(sb, Abase, Bbase, 0, tid);
    CP_COMMIT();
    for (int s = 0; s < 4; ++s) {
        CP_WAIT0();
        __syncthreads();
        if (s < 3) { gemm_issue(sb, Abase, Bbase, s + 1, tid); CP_COMMIT(); }
        uint32_t abuf = sb + (s & 1) * 16384;
        uint32_t bbuf = sb + 32768 + (s & 1) * 16384;
        #pragma unroll
        for (int kk = 0; kk < 4; ++kk) {
            uint32_t A[4][4];
            #pragma unroll
            for (int mb = 0; mb < 4; ++mb) {
                int row = wm*64 + mb*16 + a_lrow;
                ldsm4(A[mb][0], A[mb][1], A[mb][2], A[mb][3],
                      abuf + row*128 + (((2*kk + a_lch) ^ (row & 7)) << 4));
            }
            #pragma unroll
            for (int cb = 0; cb < 2; ++cb) {
                int row = wn*32 + cb*16 + b_roff;
                uint32_t b0, b1, b2, b3;
                ldsm4(b0, b1, b2, b3,
                      bbuf + row*128 + (((2*kk + b_choff) ^ (row & 7)) << 4));
                #pragma unroll
                for (int mb = 0; mb < 4; ++mb) {
                    mma_bf16(acc[mb][2*cb],   A[mb][0], A[mb][1], A[mb][2], A[mb][3], b0, b1);
                    mma_bf16(acc[mb][2*cb+1], A[mb][0], A[mb][1], A[mb][2], A[mb][3], b2, b3);
                }
            }
        }
        __syncthreads();
    }
}

__global__ __launch_bounds__(256, 2) void qkv_bf16_kernel() {
    extern __shared__ char smc[];
    uint32_t sb = smem_u32(smc);
    int tid = threadIdx.x, lane = tid & 31, w = tid >> 5;
    int wm = w & 1, wn = w >> 1;
    int g = lane >> 2, t = lane & 3;
    int b = blockIdx.z, o0 = blockIdx.y * 128, n0 = blockIdx.x * 128;
    const unsigned short* Abase = g_xh  + ((size_t)b * NPIX + n0) * CH;
    const unsigned short* Bbase = g_wbh + ((size_t)b * QKVC + o0) * CH;

    float acc[4][4][4];
    #pragma unroll
    for (int mb = 0; mb < 4; ++mb)
        #pragma unroll
        for (int nb = 0; nb < 4; ++nb)
            #pragma unroll
            for (int i = 0; i < 4; ++i) acc[mb][nb][i] = 0.f;

    gemm_bf16_core(sb, Abase, Bbase, acc, tid);

    int otile = blockIdx.y;
    if (otile < 4) {
        float fold = (otile < 2) ? QK_FOLD : 1.0f;
        unsigned short* dst = ((otile < 2) ? g_q : g_k) + (size_t)b * NPIX * CH;
        int obase = (otile < 2) ? o0 : (o0 - 256);
        #pragma unroll
        for (int nb = 0; nb < 4; ++nb) {
            int oo = o0 + wn*32 + nb*8 + 2*t;
            float2 bias = *(const float2*)&g_bb[b * QKVC + oo];
            int ol = obase + wn*32 + nb*8 + 2*t;
            #pragma unroll
            for (int mb = 0; mb < 4; ++mb) {
                int nr = n0 + wm*64 + mb*16 + g;
                __nv_bfloat162 h0 = __floats2bfloat162_rn((acc[mb][nb][0] + bias.x) * fold,
                                                          (acc[mb][nb][1] + bias.y) * fold);
                __nv_bfloat162 h1 = __floats2bfloat162_rn((acc[mb][nb][2] + bias.x) * fold,
                                                          (acc[mb][nb][3] + bias.y) * fold);
                *(__nv_bfloat162*)(dst + (size_t)nr * CH + ol)       = h0;
                *(__nv_bfloat162*)(dst + (size_t)(nr + 8) * CH + ol) = h1;
            }
        }
    } else {
        unsigned short* dst = g_v + (size_t)b * CH * NPIX;
        #pragma unroll
        for (int nb = 0; nb < 4; ++nb) {
            int oo = o0 + wn*32 + nb*8 + 2*t;
            float2 bias = *(const float2*)&g_bb[b * QKVC + oo];
            int cc = (o0 - 512) + wn*32 + nb*8 + 2*t;
            #pragma unroll
            for (int mb = 0; mb < 4; ++mb) {
                int nr = n0 + wm*64 + mb*16 + g;
                __half v0 = __float2half_rn(acc[mb][nb][0] + bias.x);
                __half v1 = __float2half_rn(acc[mb][nb][1] + bias.y);
                __half v2 = __float2half_rn(acc[mb][nb][2] + bias.x);
                __half v3 = __float2half_rn(acc[mb][nb][3] + bias.y);
                dst[(size_t)cc * NPIX + nr]           = *(unsigned short*)&v0;
                dst[(size_t)(cc + 1) * NPIX + nr]     = *(unsigned short*)&v1;
                dst[(size_t)cc * NPIX + nr + 8]       = *(unsigned short*)&v2;
                dst[(size_t)(cc + 1) * NPIX + nr + 8] = *(unsigned short*)&v3;
            }
        }
    }
}

// ---------------- K3: flash attention, BQ=64/BK=32, 2 CTAs/SM ----------------
// 8 warps: wr = w&3 -> 16 q-rows, wh = w>>2 -> 16 kv of each 32-kv tile.
// SMEM/CTA: Q 64x512B @0 (32KB), K 2x(32x512B) @32768 (32KB),
//           V 2x(256 rows x 80B) @65536 (40KB), LS @106496. Total 107008.
#define KS_OFF 32768
#define VS_OFF 65536
#define LS_OFF 106496
#define FL_SMEM 107008

__device__ __forceinline__ void issue_kv(uint32_t sb, const unsigned short* kg,
                                         const unsigned short* vg, int kb, int buf, int tid) {
    int k0 = kb * 32;
    uint32_t kbase = sb + KS_OFF + buf * 16384;
    uint32_t vbase = sb + VS_OFF + buf * 20480;
    #pragma unroll
    for (int it = 0; it < 4; ++it) {
        int t = it * 256 + tid;
        int r = t >> 5, ch = t & 31;
        CP_ASYNC(kbase + r*512 + ((ch ^ (r & 7)) << 4),
                 kg + (size_t)(k0 + r) * CH + ch * 8);
    }
    #pragma unroll
    for (int it = 0; it < 4; ++it) {
        int t = it * 256 + tid;
        int r = t >> 2, ch = t & 3;
        CP_ASYNC(vbase + r*80 + ch*16,
                 vg + (size_t)r * NPIX + k0 + ch * 8);
    }
}

__global__ __launch_bounds__(256, 2) void flash_mma_kernel() {
    extern __shared__ char sm[];
    uint32_t sb = smem_u32(sm);
    int tid = threadIdx.x, w = tid >> 5, l = tid & 31;
    int wr = w & 3, wh = w >> 2;
    int b = blockIdx.y, q0 = blockIdx.x * 64;
    const unsigned short* qg = g_q + (size_t)b * NPIX * CH;
    const unsigned short* kg = g_k + (size_t)b * NPIX * CH;
    const unsigned short* vg = g_v + (size_t)b * CH * NPIX;

    // Q tile: 64 rows x 512B
    #pragma unroll
    for (int it = 0; it < 8; ++it) {
        int t = it * 256 + tid;
        int r = t >> 5, ch = t & 31;
        uint4 val = *(const uint4*)(qg + (size_t)(q0 + r) * CH + ch * 8);
        *(uint4*)(sm + r*512 + ((ch ^ (r & 7)) << 4)) = val;
    }
    issue_kv(sb, kg, vg, 0, 0, tid);
    CP_COMMIT();

    uint32_t oacc[32][2];   // fp16x2: 16 rows x 256 d per warp
    #pragma unroll
    for (int c = 0; c < 32; ++c) { oacc[c][0] = 0u; oacc[c][1] = 0u; }
    float lsum[2] = {0.f, 0.f};

    int lg = l >> 2, lt = l & 3;
    int a_lrow = l & 15, a_lch = l >> 4;
    int b_roff = (l & 7) + ((l & 16) >> 1);
    int b_choff = (l >> 3) & 1;
    int qrow = 16*wr + a_lrow;
    uint32_t qbase = sb + qrow*512;
    int qx = qrow & 7;
    int krow = 16*wh + b_roff;
    int kx = krow & 7;
    int c2 = 2*wh + b_choff;

    for (int kb = 0; kb < 128; ++kb) {
        CP_WAIT0();
        __syncthreads();
        if (kb < 127) { issue_kv(sb, kg, vg, kb + 1, (kb + 1) & 1, tid); CP_COMMIT(); }
        uint32_t kbase = sb + KS_OFF + (kb & 1) * 16384 + krow*512;
        uint32_t vbase = sb + VS_OFF + (kb & 1) * 20480 + c2*16;

        // ---- S = Q @ K^T : 16 rows x 16 kv ----
        float sacc[2][4];
        #pragma unroll
        for (int j = 0; j < 2; ++j)
            #pragma unroll
            for (int i = 0; i < 4; ++i) sacc[j][i] = 0.f;

        #pragma unroll
        for (int kk = 0; kk < 16; ++kk) {
            uint32_t a0, a1, a2, a3, b0, b1, b2, b3;
            ldsm4(a0, a1, a2, a3, qbase + (((2*kk + a_lch) ^ qx) << 4));
            ldsm4(b0, b1, b2, b3, kbase + (((2*kk + b_choff) ^ kx) << 4));
            mma_bf16(sacc[0], a0, a1, a2, a3, b0, b1);
            mma_bf16(sacc[1], a0, a1, a2, a3, b2, b3);
        }

        // ---- softmax ----
        uint32_t pf[2][2];
        #pragma unroll
        for (int ni = 0; ni < 2; ++ni) {
            float e0 = ex2f(sacc[ni][0]), e1 = ex2f(sacc[ni][1]);
            float e2 = ex2f(sacc[ni][2]), e3 = ex2f(sacc[ni][3]);
            lsum[0] += e0 + e1;
            lsum[1] += e2 + e3;
            __half2 h0 = __floats2half2_rn(e0, e1);
            __half2 h1 = __floats2half2_rn(e2, e3);
            pf[ni][0] = *(uint32_t*)&h0;
            pf[ni][1] = *(uint32_t*)&h1;
        }

        // ---- O += P @ V : 16 rows x 256 d over this warp's 16 kv ----
        #pragma unroll
        for (int nb = 0; nb < 16; ++nb) {
            int vrow = 16*nb + b_roff;
            uint32_t b0, b1, b2, b3;
            ldsm4(b0, b1, b2, b3, vbase + vrow*80);
            mma_f16acc(oacc[2*nb],   pf[0][0], pf[0][1], pf[1][0], pf[1][1], b0, b1);
            mma_f16acc(oacc[2*nb+1], pf[0][0], pf[0][1], pf[1][0], pf[1][1], b2, b3);
        }
    }
    __syncthreads();   // loop done: Q/K/V smem dead

    // publish row sums; wh=1 dumps fp16 partial O into the arena (Q region)
    float* LS = (float*)(sm + LS_OFF);   // [64 rows][2 halves]
    #pragma unroll
    for (int rr = 0; rr < 2; ++rr) {
        float v = lsum[rr];
        v += __shfl_xor_sync(0xffffffffu, v, 1);
        v += __shfl_xor_sync(0xffffffffu, v, 2);
        LS[(16*wr + lg + 8*rr)*2 + wh] = v;
    }
    if (wh == 1) {
        int r0 = 16*wr + lg;
        int r1 = r0 + 8;
        #pragma unroll
        for (int c = 0; c < 32; ++c) {
            *(uint32_t*)(sm + r0*512 + ((c ^ (r0 & 7)) << 4) + lt*4) = oacc[c][0];
            *(uint32_t*)(sm + r1*512 + ((c ^ (r1 & 7)) << 4) + lt*4) = oacc[c][1];
        }
    }
    __syncthreads();

    if (wh == 0) {
        int r0 = 16*wr + lg;
        int r1 = r0 + 8;
        float li0 = 1.0f / (LS[r0*2] + LS[r0*2+1]);
        float li1 = 1.0f / (LS[r1*2] + LS[r1*2+1]);
        unsigned short* o0 = g_attnh + ((size_t)b * NPIX + q0 + r0) * CH + 2*lt;
        unsigned short* o1 = g_attnh + ((size_t)b * NPIX + q0 + r1) * CH + 2*lt;
        #pragma unroll
        for (int c = 0; c < 32; ++c) {
            uint32_t p0 = *(uint32_t*)(sm + r0*512 + ((c ^ (r0 & 7)) << 4) + lt*4);
            uint32_t p1 = *(uint32_t*)(sm + r1*512 + ((c ^ (r1 & 7)) << 4) + lt*4);
            float2 f0 = __half22float2(*(__half2*)&oacc[c][0]);
            float2 g0 = __half22float2(*(__half2*)&p0);
            float2 f1 = __half22float2(*(__half2*)&oacc[c][1]);
            float2 g1 = __half22float2(*(__half2*)&p1);
            __nv_bfloat162 h0 = __floats2bfloat162_rn((f0.x + g0.x) * li0, (f0.y + g0.y) * li0);
            __nv_bfloat162 h1 = __floats2bfloat162_rn((f1.x + g1.x) * li1, (f1.y + g1.y) * li1);
            *(uint32_t*)(o0 + c*8) = *(uint32_t*)&h0;
            *(uint32_t*)(o1 + c*8) = *(uint32_t*)&h1;
        }
    }
}

// ---------------- K4: proj GEMM (bf16 mma) + residual ----------------
__global__ __launch_bounds__(256, 2) void proj_bf16_kernel(const float* __restrict__ x,
                                                           const float* __restrict__ b_proj,
                                                           float* __restrict__ out) {
    extern __shared__ char smc[];
    uint32_t sb = smem_u32(smc);
    int tid = threadIdx.x, lane = tid & 31, w = tid >> 5;
    int wm = w & 1, wn = w >> 1;
    int g = lane >> 2, t = lane & 3;
    int b = blockIdx.z, o0 = blockIdx.y * 128, n0 = blockIdx.x * 128;
    const unsigned short* Abase = g_attnh + ((size_t)b * NPIX + n0) * CH;
    const unsigned short* Bbase = g_wph + (size_t)o0 * CH;

    float acc[4][4][4];
    #pragma unroll
    for (int mb = 0; mb < 4; ++mb)
        #pragma unroll
        for (int nb = 0; nb < 4; ++nb)
            #pragma unroll
            for (int i = 0; i < 4; ++i) acc[mb][nb][i] = 0.f;

    gemm_bf16_core(sb, Abase, Bbase, acc, tid);

    #pragma unroll
    for (int nb = 0; nb < 4; ++nb) {
        int oo = o0 + wn*32 + nb*8 + 2*t;
        float2 bias = *(const float2*)&b_proj[oo];
        #pragma unroll
        for (int mb = 0; mb < 4; ++mb) {
            int nr = n0 + wm*64 + mb*16 + g;
            size_t i0 = ((size_t)b * CH + oo) * NPIX + nr;
            size_t i1 = i0 + NPIX;
            out[i0]     = x[i0]     + bias.x + acc[mb][nb][0];
            out[i1]     = x[i1]     + bias.y + acc[mb][nb][1];
            out[i0 + 8] = x[i0 + 8] + bias.x + acc[mb][nb][2];
            out[i1 + 8] = x[i1 + 8] + bias.y + acc[mb][nb][3];
        }
    }
}

// ---------------- launch ----------------
extern "C" void kernel_launch(void* const* d_in, const int* in_sizes, int n_in,
                              void* d_out, int out_size) {
    const float* x      = (const float*)d_in[0];
    const float* gamma  = (const float*)d_in[1];
    const float* beta   = (const float*)d_in[2];
    const float* w_qkv  = (const float*)d_in[3];
    const float* b_qkv  = (const float*)d_in[4];
    const float* w_proj = (const float*)d_in[5];
    const float* b_proj = (const float*)d_in[6];
    float* out = (float*)d_out;

    cudaFuncSetAttribute(flash_mma_kernel, cudaFuncAttributeMaxDynamicSharedMemorySize, FL_SMEM);
    cudaFuncSetAttribute(qkv_bf16_kernel, cudaFuncAttributeMaxDynamicSharedMemorySize, GB_SMEM);
    cudaFuncSetAttribute(proj_bf16_kernel, cudaFuncAttributeMaxDynamicSharedMemorySize, GB_SMEM);

    gn_part_kernel<<<256, 256>>>(x);
    xpose_kernel<<<dim3(NPIX/64, CH/32, BATCH), 256>>>(x);
    build_wb_kernel<<<dim3(QKVC, BATCH), 256>>>(w_qkv, b_qkv, gamma, beta);
    wconv_kernel<<<64, 256>>>(w_proj);
    qkv_bf16_kernel<<<dim3(NPIX/128, QKVC/128, BATCH), 256, GB_SMEM>>>();
    flash_mma_kernel<<<dim3(NPIX/64, BATCH), 256, FL_SMEM>>>();
    proj_bf16_kernel<<<dim3(NPIX/128, CH/128, BATCH), 256, GB_SMEM>>>(x, b_proj, out);
}

// round 14
// speedup vs baseline: 1.4539x; 1.4539x over previous
#include <cuda_runtime.h>
#include <cuda_bf16.h>
#include <cuda_fp16.h>
#include <math.h>
#include <stdint.h>

#define BATCH 8
#define CH    256
#define NPIX  4096
#define QKVC  768
#define GROUPS 8
#define CPG    32
#define EPS    1e-5f
#define QK_FOLD 0.0901687145f

// ---------------- scratch ----------------
__device__ __align__(16) unsigned short g_xh[BATCH * NPIX * CH];  // bf16 x^T [b][n][c]
__device__ __align__(16) unsigned short g_q[BATCH * NPIX * CH];   // bf16 [b][n][c], q*QK_FOLD
__device__ __align__(16) unsigned short g_k[BATCH * NPIX * CH];   // bf16 [b][n][c]
__device__ __align__(16) unsigned short g_v[BATCH * CH * NPIX];   // fp16 [b][c][n]
__device__ __align__(16) unsigned short g_attnh[BATCH * NPIX * CH]; // bf16 [b][n][c]
__device__ __align__(16) unsigned short g_wbh[BATCH * QKVC * CH]; // bf16 folded qkv weights
__device__ __align__(16) unsigned short g_wph[CH * CH];           // bf16 w_proj [o][c]
__device__ float g_bb  [BATCH * QKVC];
__device__ float g_part[BATCH * GROUPS * 64 * 2];  // per (b,g,ntile): sum, sumsq

// ================= helpers =================
__device__ __forceinline__ uint32_t smem_u32(const void* p) {
    uint32_t a;
    asm("{ .reg .u64 t; cvta.to.shared.u64 t, %1; cvt.u32.u64 %0, t; }" : "=r"(a) : "l"(p));
    return a;
}
__device__ __forceinline__ float ex2f(float x) {
    float r; asm("ex2.approx.f32 %0, %1;" : "=f"(r) : "f"(x)); return r;
}
__device__ __forceinline__ void ldsm4(uint32_t& r0, uint32_t& r1, uint32_t& r2, uint32_t& r3,
                                      uint32_t addr) {
    asm volatile("ldmatrix.sync.aligned.m8n8.x4.shared.b16 {%0,%1,%2,%3}, [%4];"
                 : "=r"(r0), "=r"(r1), "=r"(r2), "=r"(r3) : "r"(addr));
}
__device__ __forceinline__ void mma_bf16(float* d, uint32_t a0, uint32_t a1, uint32_t a2,
                                         uint32_t a3, uint32_t b0, uint32_t b1) {
    asm volatile("mma.sync.aligned.m16n8k16.row.col.f32.bf16.bf16.f32 "
                 "{%0,%1,%2,%3}, {%4,%5,%6,%7}, {%8,%9}, {%0,%1,%2,%3};"
                 : "+f"(d[0]), "+f"(d[1]), "+f"(d[2]), "+f"(d[3])
                 : "r"(a0), "r"(a1), "r"(a2), "r"(a3), "r"(b0), "r"(b1));
}
__device__ __forceinline__ void mma_f16acc(uint32_t* d, uint32_t a0, uint32_t a1, uint32_t a2,
                                           uint32_t a3, uint32_t b0, uint32_t b1) {
    asm volatile("mma.sync.aligned.m16n8k16.row.col.f16.f16.f16.f16 "
                 "{%0,%1}, {%2,%3,%4,%5}, {%6,%7}, {%0,%1};"
                 : "+r"(d[0]), "+r"(d[1])
                 : "r"(a0), "r"(a1), "r"(a2), "r"(a3), "r"(b0), "r"(b1));
}
#define CP_ASYNC(dst, src) \
    asm volatile("cp.async.cg.shared.global [%0], [%1], 16;" :: "r"(dst), "l"(src))
#define CP_COMMIT() asm volatile("cp.async.commit_group;" ::: "memory")
#define CP_WAIT0()  asm volatile("cp.async.wait_group 0;" ::: "memory")

// ---------------- K0: transpose x -> bf16 [b][n][c] + gn partial sums ----------------
// grid (NPIX/64, CH/32=GROUPS, BATCH); blockIdx.y IS the group index.
__global__ void xpose_kernel(const float* __restrict__ x) {
    __shared__ float ts[32][65];
    __shared__ float rs[256], rs2[256];
    int b = blockIdx.z, g = blockIdx.y, n0 = blockIdx.x * 64;
    int c0 = g * 32;
    const float* xb = x + ((size_t)b * CH + c0) * NPIX + n0;
    int tid = threadIdx.x;
    float s = 0.f, s2 = 0.f;
    #pragma unroll
    for (int it = 0; it < 2; ++it) {
        int p = it * 256 + tid;
        int r = p >> 4, q = p & 15;
        float4 v = *(const float4*)(xb + (size_t)r * NPIX + q * 4);
        ts[r][q*4+0] = v.x; ts[r][q*4+1] = v.y; ts[r][q*4+2] = v.z; ts[r][q*4+3] = v.w;
        s  += v.x + v.y + v.z + v.w;
        s2 += v.x*v.x + v.y*v.y + v.z*v.z + v.w*v.w;
    }
    rs[tid] = s; rs2[tid] = s2;
    __syncthreads();
    // bf16 transpose store
    int nr = tid >> 2, cq = tid & 3;
    union { __nv_bfloat162 h[4]; uint4 u; } pk;
    #pragma unroll
    for (int j = 0; j < 4; ++j)
        pk.h[j] = __floats2bfloat162_rn(ts[cq*8 + 2*j][nr], ts[cq*8 + 2*j + 1][nr]);
    *(uint4*)(g_xh + ((size_t)b * NPIX + n0 + nr) * CH + c0 + cq * 8) = pk.u;
    // block reduction for groupnorm partials
    for (int o = 128; o > 0; o >>= 1) {
        if (tid < o) { rs[tid] += rs[tid+o]; rs2[tid] += rs2[tid+o]; }
        __syncthreads();
    }
    if (tid == 0) {
        int idx = ((b * GROUPS + g) * 64 + blockIdx.x) * 2;
        g_part[idx]     = rs[0];
        g_part[idx + 1] = rs2[0];
    }
}

// ---------------- K1: stats finalize + fold affine into qkv weights + wconv ----------------
__global__ void build_wb_kernel(const float* __restrict__ w_qkv,
                                const float* __restrict__ b_qkv,
                                const float* __restrict__ gamma,
                                const float* __restrict__ beta,
                                const float* __restrict__ w_proj) {
    int o = blockIdx.x, b = blockIdx.y, c = threadIdx.x;
    int g = c >> 5;
    const float* pp = g_part + (b * GROUPS + g) * 128;
    float s = 0.f, s2 = 0.f;
    #pragma unroll 8
    for (int i = 0; i < 64; ++i) { s += pp[2*i]; s2 += pp[2*i + 1]; }
    float mean = s  * (1.0f / 131072.0f);
    float var  = s2 * (1.0f / 131072.0f) - mean * mean;
    float rinv = rsqrtf(var + EPS);
    float sc = rinv * gamma[c];
    float tt = beta[c] - mean * sc;
    float w = w_qkv[o * CH + c];
    __nv_bfloat16 wh = __float2bfloat16(w * sc);
    g_wbh[((size_t)b * QKVC + o) * CH + c] = *(unsigned short*)&wh;
    // fold w_proj conversion into the first batch's first 256 blocks
    if (b == 0 && o < CH) {
        __nv_bfloat16 wp = __float2bfloat16(w_proj[o * CH + c]);
        g_wph[o * CH + c] = *(unsigned short*)&wp;
    }
    __shared__ float red[256];
    red[c] = w * tt;
    __syncthreads();
    for (int off = 128; off > 0; off >>= 1) {
        if (c < off) red[c] += red[c + off];
        __syncthreads();
    }
    if (c == 0) g_bb[b * QKVC + o] = b_qkv[o] + red[0];
}

// ---------------- K2: QKV GEMM (bf16 mma) ----------------
#define GB_SMEM 65536

__device__ __forceinline__ void gemm_issue(uint32_t sb, const unsigned short* Abase,
                                           const unsigned short* Bbase, int s, int tid) {
    int buf = s & 1, c0 = s * 64;
    uint32_t adst = sb + buf * 16384;
    uint32_t bdst = sb + 32768 + buf * 16384;
    #pragma unroll
    for (int it = 0; it < 4; ++it) {
        int t = it * 256 + tid;
        int r = t >> 3, ch = t & 7;
        CP_ASYNC(adst + r*128 + ((ch ^ (r & 7)) << 4), Abase + (size_t)r * CH + c0 + ch * 8);
    }
    #pragma unroll
    for (int it = 0; it < 4; ++it) {
        int t = it * 256 + tid;
        int r = t >> 3, ch = t & 7;
        CP_ASYNC(bdst + r*128 + ((ch ^ (r & 7)) << 4), Bbase + (size_t)r * CH + c0 + ch * 8);
    }
}

__device__ __forceinline__ void gemm_bf16_core(uint32_t sb, const unsigned short* Abase,
                                               const unsigned short* Bbase,
                                               float acc[4][4][4], int tid) {
    int l = tid & 31, w = tid >> 5;
    int wm = w & 1, wn = w >> 1;
    int a_lrow = l & 15, a_lch = l >> 4;
    int b_roff = (l & 7) + ((l & 16) >> 1);
    int b_choff = (l >> 3) & 1;

    gemm_issue(sb, Abase, Bbase, 0, tid);
    CP_COMMIT();
    for (int s = 0; s < 4; ++s) {
        CP_WAIT0();
        __syncthreads();
        if (s < 3) { gemm_issue(sb, Abase, Bbase, s + 1, tid); CP_COMMIT(); }
        uint32_t abuf = sb + (s & 1) * 16384;
        uint32_t bbuf = sb + 32768 + (s & 1) * 16384;
        #pragma unroll
        for (int kk = 0; kk < 4; ++kk) {
            uint32_t A[4][4];
            #pragma unroll
            for (int mb = 0; mb < 4; ++mb) {
                int row = wm*64 + mb*16 + a_lrow;
                ldsm4(A[mb][0], A[mb][1], A[mb][2], A[mb][3],
                      abuf + row*128 + (((2*kk + a_lch) ^ (row & 7)) << 4));
            }
            #pragma unroll
            for (int cb = 0; cb < 2; ++cb) {
                int row = wn*32 + cb*16 + b_roff;
                uint32_t b0, b1, b2, b3;
                ldsm4(b0, b1, b2, b3,
                      bbuf + row*128 + (((2*kk + b_choff) ^ (row & 7)) << 4));
                #pragma unroll
                for (int mb = 0; mb < 4; ++mb) {
                    mma_bf16(acc[mb][2*cb],   A[mb][0], A[mb][1], A[mb][2], A[mb][3], b0, b1);
                    mma_bf16(acc[mb][2*cb+1], A[mb][0], A[mb][1], A[mb][2], A[mb][3], b2, b3);
                }
            }
        }
        __syncthreads();
    }
}

__global__ __launch_bounds__(256, 2) void qkv_bf16_kernel() {
    extern __shared__ char smc[];
    uint32_t sb = smem_u32(smc);
    int tid = threadIdx.x, lane = tid & 31, w = tid >> 5;
    int wm = w & 1, wn = w >> 1;
    int g = lane >> 2, t = lane & 3;
    int b = blockIdx.z, o0 = blockIdx.y * 128, n0 = blockIdx.x * 128;
    const unsigned short* Abase = g_xh  + ((size_t)b * NPIX + n0) * CH;
    const unsigned short* Bbase = g_wbh + ((size_t)b * QKVC + o0) * CH;

    float acc[4][4][4];
    #pragma unroll
    for (int mb = 0; mb < 4; ++mb)
        #pragma unroll
        for (int nb = 0; nb < 4; ++nb)
            #pragma unroll
            for (int i = 0; i < 4; ++i) acc[mb][nb][i] = 0.f;

    gemm_bf16_core(sb, Abase, Bbase, acc, tid);

    int otile = blockIdx.y;
    if (otile < 4) {
        float fold = (otile < 2) ? QK_FOLD : 1.0f;
        unsigned short* dst = ((otile < 2) ? g_q : g_k) + (size_t)b * NPIX * CH;
        int obase = (otile < 2) ? o0 : (o0 - 256);
        #pragma unroll
        for (int nb = 0; nb < 4; ++nb) {
            int oo = o0 + wn*32 + nb*8 + 2*t;
            float2 bias = *(const float2*)&g_bb[b * QKVC + oo];
            int ol = obase + wn*32 + nb*8 + 2*t;
            #pragma unroll
            for (int mb = 0; mb < 4; ++mb) {
                int nr = n0 + wm*64 + mb*16 + g;
                __nv_bfloat162 h0 = __floats2bfloat162_rn((acc[mb][nb][0] + bias.x) * fold,
                                                          (acc[mb][nb][1] + bias.y) * fold);
                __nv_bfloat162 h1 = __floats2bfloat162_rn((acc[mb][nb][2] + bias.x) * fold,
                                                          (acc[mb][nb][3] + bias.y) * fold);
                *(__nv_bfloat162*)(dst + (size_t)nr * CH + ol)       = h0;
                *(__nv_bfloat162*)(dst + (size_t)(nr + 8) * CH + ol) = h1;
            }
        }
    } else {
        unsigned short* dst = g_v + (size_t)b * CH * NPIX;
        #pragma unroll
        for (int nb = 0; nb < 4; ++nb) {
            int oo = o0 + wn*32 + nb*8 + 2*t;
            float2 bias = *(const float2*)&g_bb[b * QKVC + oo];
            int cc = (o0 - 512) + wn*32 + nb*8 + 2*t;
            #pragma unroll
            for (int mb = 0; mb < 4; ++mb) {
                int nr = n0 + wm*64 + mb*16 + g;
                __half v0 = __float2half_rn(acc[mb][nb][0] + bias.x);
                __half v1 = __float2half_rn(acc[mb][nb][1] + bias.y);
                __half v2 = __float2half_rn(acc[mb][nb][2] + bias.x);
                __half v3 = __float2half_rn(acc[mb][nb][3] + bias.y);
                dst[(size_t)cc * NPIX + nr]           = *(unsigned short*)&v0;
                dst[(size_t)(cc + 1) * NPIX + nr]     = *(unsigned short*)&v1;
                dst[(size_t)cc * NPIX + nr + 8]       = *(unsigned short*)&v2;
                dst[(size_t)(cc + 1) * NPIX + nr + 8] = *(unsigned short*)&v3;
            }
        }
    }
}

// ---------------- K3: flash attention (round-11 exact) ----------------
#define KS_OFF 65536
#define VS_OFF 131072
#define FL_SMEM 196608
#define OH_OFF 4096
#define OH_STR 528

__device__ __forceinline__ void issue_kv(uint32_t sb, const unsigned short* kg,
                                         const unsigned short* vg, int kb, int buf, int tid) {
    int k0 = kb * 64;
    uint32_t kbase = sb + KS_OFF + buf * 32768;
    uint32_t vbase = sb + VS_OFF + buf * 32768;
    #pragma unroll
    for (int it = 0; it < 8; ++it) {
        int t = it * 256 + tid;
        int r = t >> 5, ch = t & 31;
        CP_ASYNC(kbase + r*512 + ((ch ^ (r & 7)) << 4),
                 kg + (size_t)(k0 + r) * CH + ch * 8);
    }
    #pragma unroll
    for (int it = 0; it < 8; ++it) {
        int t = it * 256 + tid;
        int r = t >> 3, ch = t & 7;
        CP_ASYNC(vbase + r*128 + ((ch ^ (r & 7)) << 4),
                 vg + (size_t)r * NPIX + k0 + ch * 8);
    }
}

__global__ __launch_bounds__(256, 1) void flash_mma_kernel() {
    extern __shared__ char sm[];
    uint32_t sb = smem_u32(sm);
    int tid = threadIdx.x, w = tid >> 5, l = tid & 31;
    int wr = w & 3, wh = w >> 2;
    int b = blockIdx.y, q0 = blockIdx.x * 128;
    const unsigned short* qg = g_q + (size_t)b * NPIX * CH;
    const unsigned short* kg = g_k + (size_t)b * NPIX * CH;
    const unsigned short* vg = g_v + (size_t)b * CH * NPIX;

    #pragma unroll
    for (int it = 0; it < 16; ++it) {
        int t = it * 256 + tid;
        int r = t >> 5, ch = t & 31;
        uint4 val = *(const uint4*)(qg + (size_t)(q0 + r) * CH + ch * 8);
        *(uint4*)(sm + r*512 + ((ch ^ (r & 7)) << 4)) = val;
    }
    issue_kv(sb, kg, vg, 0, 0, tid);
    CP_COMMIT();

    uint32_t oacc[2][32][2];
    #pragma unroll
    for (int mi = 0; mi < 2; ++mi)
        #pragma unroll
        for (int c = 0; c < 32; ++c) { oacc[mi][c][0] = 0u; oacc[mi][c][1] = 0u; }
    float lsum[2][2] = {{0.f, 0.f}, {0.f, 0.f}};

    int lg = l >> 2, lt = l & 3;
    int a_lrow = l & 15, a_lch = l >> 4;
    int b_roff = (l & 7) + ((l & 16) >> 1);
    int b_choff = (l >> 3) & 1;

    for (int kb = 0; kb < 64; ++kb) {
        CP_WAIT0();
        __syncthreads();
        if (kb < 63) { issue_kv(sb, kg, vg, kb + 1, (kb + 1) & 1, tid); CP_COMMIT(); }
        uint32_t kbase = sb + KS_OFF + (kb & 1) * 32768;
        uint32_t vbase = sb + VS_OFF + (kb & 1) * 32768;

        float sacc[2][4][4];
        #pragma unroll
        for (int mi = 0; mi < 2; ++mi)
            #pragma unroll
            for (int j = 0; j < 4; ++j)
                #pragma unroll
                for (int i = 0; i < 4; ++i) sacc[mi][j][i] = 0.f;

        #pragma unroll
        for (int kk = 0; kk < 16; ++kk) {
            uint32_t A[2][4];
            #pragma unroll
            for (int mi = 0; mi < 2; ++mi) {
                int qrow = 32*wr + 16*mi + a_lrow;
                ldsm4(A[mi][0], A[mi][1], A[mi][2], A[mi][3],
                      sb + qrow*512 + (((2*kk + a_lch) ^ (qrow & 7)) << 4));
            }
            #pragma unroll
            for (int cb = 0; cb < 2; ++cb) {
                int krow = 32*wh + 16*cb + b_roff;
                uint32_t b0, b1, b2, b3;
                ldsm4(b0, b1, b2, b3,
                      kbase + krow*512 + (((2*kk + b_choff) ^ (krow & 7)) << 4));
                #pragma unroll
                for (int mi = 0; mi < 2; ++mi) {
                    mma_bf16(sacc[mi][2*cb],   A[mi][0], A[mi][1], A[mi][2], A[mi][3], b0, b1);
                    mma_bf16(sacc[mi][2*cb+1], A[mi][0], A[mi][1], A[mi][2], A[mi][3], b2, b3);
                }
            }
        }

        uint32_t pf[2][4][2];
        #pragma unroll
        for (int mi = 0; mi < 2; ++mi) {
            #pragma unroll
            for (int ni = 0; ni < 4; ++ni) {
                float e0 = ex2f(sacc[mi][ni][0]), e1 = ex2f(sacc[mi][ni][1]);
                float e2 = ex2f(sacc[mi][ni][2]), e3 = ex2f(sacc[mi][ni][3]);
                lsum[mi][0] += e0 + e1;
                lsum[mi][1] += e2 + e3;
                __half2 h0 = __floats2half2_rn(e0, e1);
                __half2 h1 = __floats2half2_rn(e2, e3);
                pf[mi][ni][0] = *(uint32_t*)&h0;
                pf[mi][ni][1] = *(uint32_t*)&h1;
            }
        }

        #pragma unroll
        for (int j2 = 0; j2 < 2; ++j2) {
            int c2 = 2*(2*wh + j2) + b_choff;
            #pragma unroll
            for (int nb = 0; nb < 16; ++nb) {
                int vrow = 16*nb + b_roff;
                uint32_t b0, b1, b2, b3;
                ldsm4(b0, b1, b2, b3,
                      vbase + vrow*128 + ((c2 ^ (vrow & 7)) << 4));
                #pragma unroll
                for (int mi = 0; mi < 2; ++mi) {
                    mma_f16acc(oacc[mi][2*nb],
                               pf[mi][2*j2][0], pf[mi][2*j2][1],
                               pf[mi][2*j2+1][0], pf[mi][2*j2+1][1], b0, b1);
                    mma_f16acc(oacc[mi][2*nb+1],
                               pf[mi][2*j2][0], pf[mi][2*j2][1],
                               pf[mi][2*j2+1][0], pf[mi][2*j2+1][1], b2, b3);
                }
            }
        }
    }
    __syncthreads();

    float* LS = (float*)sm;
    #pragma unroll
    for (int mi = 0; mi < 2; ++mi)
        #pragma unroll
        for (int rr = 0; rr < 2; ++rr) {
            float v = lsum[mi][rr];
            v += __shfl_xor_sync(0xffffffffu, v, 1);
            v += __shfl_xor_sync(0xffffffffu, v, 2);
            LS[(32*wr + 16*mi + lg + 8*rr)*2 + wh] = v;
        }
    if (wh == 1) {
        #pragma unroll
        for (int mi = 0; mi < 2; ++mi) {
            int r0 = 32*wr + 16*mi + lg;
            #pragma unroll
            for (int c = 0; c < 32; ++c) {
                *(uint32_t*)(sm + OH_OFF + r0*OH_STR + (c*8 + 2*lt)*2)     = oacc[mi][c][0];
                *(uint32_t*)(sm + OH_OFF + (r0+8)*OH_STR + (c*8 + 2*lt)*2) = oacc[mi][c][1];
            }
        }
    }
    __syncthreads();

    if (wh == 0) {
        #pragma unroll
        for (int mi = 0; mi < 2; ++mi) {
            int lrow = 32*wr + 16*mi + lg;
            float li0 = 1.0f / (LS[lrow*2] + LS[lrow*2+1]);
            float li1 = 1.0f / (LS[(lrow+8)*2] + LS[(lrow+8)*2+1]);
            unsigned short* o0 = g_attnh + ((size_t)b * NPIX + q0 + lrow) * CH + 2*lt;
            unsigned short* o1 = o0 + 8 * CH;
            #pragma unroll
            for (int c = 0; c < 32; ++c) {
                uint32_t p0 = *(uint32_t*)(sm + OH_OFF + lrow*OH_STR + (c*8 + 2*lt)*2);
                uint32_t p1 = *(uint32_t*)(sm + OH_OFF + (lrow+8)*OH_STR + (c*8 + 2*lt)*2);
                float2 f0 = __half22float2(*(__half2*)&oacc[mi][c][0]);
                float2 g0 = __half22float2(*(__half2*)&p0);
                float2 f1 = __half22float2(*(__half2*)&oacc[mi][c][1]);
                float2 g1 = __half22float2(*(__half2*)&p1);
                __nv_bfloat162 h0 = __floats2bfloat162_rn((f0.x + g0.x) * li0, (f0.y + g0.y) * li0);
                __nv_bfloat162 h1 = __floats2bfloat162_rn((f1.x + g1.x) * li1, (f1.y + g1.y) * li1);
                *(uint32_t*)(o0 + c*8) = *(uint32_t*)&h0;
                *(uint32_t*)(o1 + c*8) = *(uint32_t*)&h1;
            }
        }
    }
}

// ---------------- K4: proj GEMM (bf16 mma) + residual ----------------
__global__ __launch_bounds__(256, 2) void proj_bf16_kernel(const float* __restrict__ x,
                                                           const float* __restrict__ b_proj,
                                                           float* __restrict__ out) {
    extern __shared__ char smc[];
    uint32_t sb = smem_u32(smc);
    int tid = threadIdx.x, lane = tid & 31, w = tid >> 5;
    int wm = w & 1, wn = w >> 1;
    int g = lane >> 2, t = lane & 3;
    int b = blockIdx.z, o0 = blockIdx.y * 128, n0 = blockIdx.x * 128;
    const unsigned short* Abase = g_attnh + ((size_t)b * NPIX + n0) * CH;
    const unsigned short* Bbase = g_wph + (size_t)o0 * CH;

    float acc[4][4][4];
    #pragma unroll
    for (int mb = 0; mb < 4; ++mb)
        #pragma unroll
        for (int nb = 0; nb < 4; ++nb)
            #pragma unroll
            for (int i = 0; i < 4; ++i) acc[mb][nb][i] = 0.f;

    gemm_bf16_core(sb, Abase, Bbase, acc, tid);

    #pragma unroll
    for (int nb = 0; nb < 4; ++nb) {
        int oo = o0 + wn*32 + nb*8 + 2*t;
        float2 bias = *(const float2*)&b_proj[oo];
        #pragma unroll
        for (int mb = 0; mb < 4; ++mb) {
            int nr = n0 + wm*64 + mb*16 + g;
            size_t i0 = ((size_t)b * CH + oo) * NPIX + nr;
            size_t i1 = i0 + NPIX;
            out[i0]     = x[i0]     + bias.x + acc[mb][nb][0];
            out[i1]     = x[i1]     + bias.y + acc[mb][nb][1];
            out[i0 + 8] = x[i0 + 8] + bias.x + acc[mb][nb][2];
            out[i1 + 8] = x[i1 + 8] + bias.y + acc[mb][nb][3];
        }
    }
}

// ---------------- launch ----------------
extern "C" void kernel_launch(void* const* d_in, const int* in_sizes, int n_in,
                              void* d_out, int out_size) {
    const float* x      = (const float*)d_in[0];
    const float* gamma  = (const float*)d_in[1];
    const float* beta   = (const float*)d_in[2];
    const float* w_qkv  = (const float*)d_in[3];
    const float* b_qkv  = (const float*)d_in[4];
    const float* w_proj = (const float*)d_in[5];
    const float* b_proj = (const float*)d_in[6];
    float* out = (float*)d_out;

    cudaFuncSetAttribute(flash_mma_kernel, cudaFuncAttributeMaxDynamicSharedMemorySize, FL_SMEM);
    cudaFuncSetAttribute(qkv_bf16_kernel, cudaFuncAttributeMaxDynamicSharedMemorySize, GB_SMEM);
    cudaFuncSetAttribute(proj_bf16_kernel, cudaFuncAttributeMaxDynamicSharedMemorySize, GB_SMEM);

    xpose_kernel<<<dim3(NPIX/64, GROUPS, BATCH), 256>>>(x);
    build_wb_kernel<<<dim3(QKVC, BATCH), 256>>>(w_qkv, b_qkv, gamma, beta, w_proj);
    qkv_bf16_kernel<<<dim3(NPIX/128, QKVC/128, BATCH), 256, GB_SMEM>>>();
    flash_mma_kernel<<<dim3(NPIX/128, BATCH), 256, FL_SMEM>>>();
    proj_bf16_kernel<<<dim3(NPIX/128, CH/128, BATCH), 256, GB_SMEM>>>(x, b_proj, out);
}

// round 15
// speedup vs baseline: 1.5120x; 1.0400x over previous
#include <cuda_runtime.h>
#include <cuda_bf16.h>
#include <cuda_fp16.h>
#include <math.h>
#include <stdint.h>

#define BATCH 8
#define CH    256
#define NPIX  4096
#define QKVC  768
#define GROUPS 8
#define CPG    32
#define EPS    1e-5f
#define QK_FOLD 0.0901687145f

// ---------------- scratch ----------------
__device__ __align__(16) unsigned short g_xh[BATCH * NPIX * CH];  // bf16 x^T [b][n][c]
__device__ __align__(16) unsigned short g_q[BATCH * NPIX * CH];   // bf16 [b][n][c], q*QK_FOLD
__device__ __align__(16) unsigned short g_k[BATCH * NPIX * CH];   // bf16 [b][n][c]
__device__ __align__(16) unsigned short g_v[BATCH * CH * NPIX];   // fp16 [b][c][n]
__device__ __align__(16) unsigned short g_attnh[BATCH * NPIX * CH]; // bf16 [b][n][c]
__device__ __align__(16) unsigned short g_wbh[BATCH * QKVC * CH]; // bf16 folded qkv weights
__device__ __align__(16) unsigned short g_wph[CH * CH];           // bf16 w_proj [o][c]
__device__ float g_bb  [BATCH * QKVC];
__device__ float g_part[BATCH * GROUPS * 8];   // 4 partials x (sum, sumsq) per (b,g)

// ================= helpers =================
__device__ __forceinline__ uint32_t smem_u32(const void* p) {
    uint32_t a;
    asm("{ .reg .u64 t; cvta.to.shared.u64 t, %1; cvt.u32.u64 %0, t; }" : "=r"(a) : "l"(p));
    return a;
}
__device__ __forceinline__ float ex2f(float x) {
    float r; asm("ex2.approx.f32 %0, %1;" : "=f"(r) : "f"(x)); return r;
}
__device__ __forceinline__ void ldsm4(uint32_t& r0, uint32_t& r1, uint32_t& r2, uint32_t& r3,
                                      uint32_t addr) {
    asm volatile("ldmatrix.sync.aligned.m8n8.x4.shared.b16 {%0,%1,%2,%3}, [%4];"
                 : "=r"(r0), "=r"(r1), "=r"(r2), "=r"(r3) : "r"(addr));
}
__device__ __forceinline__ void mma_bf16(float* d, uint32_t a0, uint32_t a1, uint32_t a2,
                                         uint32_t a3, uint32_t b0, uint32_t b1) {
    asm volatile("mma.sync.aligned.m16n8k16.row.col.f32.bf16.bf16.f32 "
                 "{%0,%1,%2,%3}, {%4,%5,%6,%7}, {%8,%9}, {%0,%1,%2,%3};"
                 : "+f"(d[0]), "+f"(d[1]), "+f"(d[2]), "+f"(d[3])
                 : "r"(a0), "r"(a1), "r"(a2), "r"(a3), "r"(b0), "r"(b1));
}
__device__ __forceinline__ void mma_f16acc(uint32_t* d, uint32_t a0, uint32_t a1, uint32_t a2,
                                           uint32_t a3, uint32_t b0, uint32_t b1) {
    asm volatile("mma.sync.aligned.m16n8k16.row.col.f16.f16.f16.f16 "
                 "{%0,%1}, {%2,%3,%4,%5}, {%6,%7}, {%0,%1};"
                 : "+r"(d[0]), "+r"(d[1])
                 : "r"(a0), "r"(a1), "r"(a2), "r"(a3), "r"(b0), "r"(b1));
}
#define CP_ASYNC(dst, src) \
    asm volatile("cp.async.cg.shared.global [%0], [%1], 16;" :: "r"(dst), "l"(src))
#define CP_COMMIT() asm volatile("cp.async.commit_group;" ::: "memory")
#define CP_WAIT0()  asm volatile("cp.async.wait_group 0;" ::: "memory")

// ---------------- K0: groupnorm partial sums (+ w_proj conversion fold) ----------------
__global__ void gn_part_kernel(const float* __restrict__ x,
                               const float* __restrict__ w_proj) {
    int id = blockIdx.x;
    int b = id >> 5, g = (id >> 2) & 7, qtr = id & 3;
    // fold: blocks 0-63 also convert w_proj (64 blocks x 256 threads x 1 float4)
    if (id < 64) {
        int i = id * 256 + threadIdx.x;
        float4 v = ((const float4*)w_proj)[i];
        union { __nv_bfloat162 h[2]; uint2 u; } pk;
        pk.h[0] = __floats2bfloat162_rn(v.x, v.y);
        pk.h[1] = __floats2bfloat162_rn(v.z, v.w);
        ((uint2*)g_wph)[i] = pk.u;
    }
    const float4* xv = (const float4*)(x + ((size_t)b * CH + g * CPG) * NPIX) + qtr * 8192;
    float s = 0.f, s2 = 0.f;
    for (int i = threadIdx.x; i < 8192; i += 256) {
        float4 v = xv[i];
        s  += v.x + v.y + v.z + v.w;
        s2 += v.x*v.x + v.y*v.y + v.z*v.z + v.w*v.w;
    }
    __shared__ float rs[256], rs2[256];
    rs[threadIdx.x] = s; rs2[threadIdx.x] = s2;
    __syncthreads();
    for (int o = 128; o > 0; o >>= 1) {
        if (threadIdx.x < o) { rs[threadIdx.x] += rs[threadIdx.x+o]; rs2[threadIdx.x] += rs2[threadIdx.x+o]; }
        __syncthreads();
    }
    if (threadIdx.x == 0) {
        g_part[(b * 8 + g) * 8 + qtr * 2]     = rs[0];
        g_part[(b * 8 + g) * 8 + qtr * 2 + 1] = rs2[0];
    }
}

// ---------------- K0b: transpose x -> bf16 [b][n][c] ----------------
__global__ void xpose_kernel(const float* __restrict__ x) {
    __shared__ float ts[32][65];
    int b = blockIdx.z, c0 = blockIdx.y * 32, n0 = blockIdx.x * 64;
    const float* xb = x + ((size_t)b * CH + c0) * NPIX + n0;
    int tid = threadIdx.x;
    #pragma unroll
    for (int it = 0; it < 2; ++it) {
        int p = it * 256 + tid;
        int r = p >> 4, q = p & 15;
        float4 v = *(const float4*)(xb + (size_t)r * NPIX + q * 4);
        ts[r][q*4+0] = v.x; ts[r][q*4+1] = v.y; ts[r][q*4+2] = v.z; ts[r][q*4+3] = v.w;
    }
    __syncthreads();
    int nr = tid >> 2, cq = tid & 3;
    union { __nv_bfloat162 h[4]; uint4 u; } pk;
    #pragma unroll
    for (int j = 0; j < 4; ++j)
        pk.h[j] = __floats2bfloat162_rn(ts[cq*8 + 2*j][nr], ts[cq*8 + 2*j + 1][nr]);
    *(uint4*)(g_xh + ((size_t)b * NPIX + n0 + nr) * CH + c0 + cq * 8) = pk.u;
}

// ---------------- K1: stats finalize + fold affine into qkv weights ----------------
__global__ void build_wb_kernel(const float* __restrict__ w_qkv,
                                const float* __restrict__ b_qkv,
                                const float* __restrict__ gamma,
                                const float* __restrict__ beta) {
    int o = blockIdx.x, b = blockIdx.y, c = threadIdx.x;
    int g = c >> 5;
    const float* pp = g_part + (b * 8 + g) * 8;
    float s  = (pp[0] + pp[2]) + (pp[4] + pp[6]);
    float s2 = (pp[1] + pp[3]) + (pp[5] + pp[7]);
    float mean = s  * (1.0f / 131072.0f);
    float var  = s2 * (1.0f / 131072.0f) - mean * mean;
    float rinv = rsqrtf(var + EPS);
    float sc = rinv * gamma[c];
    float tt = beta[c] - mean * sc;
    float w = w_qkv[o * CH + c];
    __nv_bfloat16 wh = __float2bfloat16(w * sc);
    g_wbh[((size_t)b * QKVC + o) * CH + c] = *(unsigned short*)&wh;
    __shared__ float red[256];
    red[c] = w * tt;
    __syncthreads();
    for (int off = 128; off > 0; off >>= 1) {
        if (c < off) red[c] += red[c + off];
        __syncthreads();
    }
    if (c == 0) g_bb[b * QKVC + o] = b_qkv[o] + red[0];
}

// ---------------- K2: QKV GEMM (bf16 mma) ----------------
#define GB_SMEM 65536

__device__ __forceinline__ void gemm_issue(uint32_t sb, const unsigned short* Abase,
                                           const unsigned short* Bbase, int s, int tid) {
    int buf = s & 1, c0 = s * 64;
    uint32_t adst = sb + buf * 16384;
    uint32_t bdst = sb + 32768 + buf * 16384;
    #pragma unroll
    for (int it = 0; it < 4; ++it) {
        int t = it * 256 + tid;
        int r = t >> 3, ch = t & 7;
        CP_ASYNC(adst + r*128 + ((ch ^ (r & 7)) << 4), Abase + (size_t)r * CH + c0 + ch * 8);
    }
    #pragma unroll
    for (int it = 0; it < 4; ++it) {
        int t = it * 256 + tid;
        int r = t >> 3, ch = t & 7;
        CP_ASYNC(bdst + r*128 + ((ch ^ (r & 7)) << 4), Bbase + (size_t)r * CH + c0 + ch * 8);
    }
}

__device__ __forceinline__ void gemm_bf16_core(uint32_t sb, const unsigned short* Abase,
                                               const unsigned short* Bbase,
                                               float acc[4][4][4], int tid) {
    int l = tid & 31, w = tid >> 5;
    int wm = w & 1, wn = w >> 1;
    int a_lrow = l & 15, a_lch = l >> 4;
    int b_roff = (l & 7) + ((l & 16) >> 1);
    int b_choff = (l >> 3) & 1;

    gemm_issue(sb, Abase, Bbase, 0, tid);
    CP_COMMIT();
    for (int s = 0; s < 4; ++s) {
        CP_WAIT0();
        __syncthreads();   // loads for slice s ready; all reads of the buffer
                           // being overwritten by issue(s+1) completed (prev iter)
        if (s < 3) { gemm_issue(sb, Abase, Bbase, s + 1, tid); CP_COMMIT(); }
        uint32_t abuf = sb + (s & 1) * 16384;
        uint32_t bbuf = sb + 32768 + (s & 1) * 16384;
        #pragma unroll
        for (int kk = 0; kk < 4; ++kk) {
            uint32_t A[4][4];
            #pragma unroll
            for (int mb = 0; mb < 4; ++mb) {
                int row = wm*64 + mb*16 + a_lrow;
                ldsm4(A[mb][0], A[mb][1], A[mb][2], A[mb][3],
                      abuf + row*128 + (((2*kk + a_lch) ^ (row & 7)) << 4));
            }
            #pragma unroll
            for (int cb = 0; cb < 2; ++cb) {
                int row = wn*32 + cb*16 + b_roff;
                uint32_t b0, b1, b2, b3;
                ldsm4(b0, b1, b2, b3,
                      bbuf + row*128 + (((2*kk + b_choff) ^ (row & 7)) << 4));
                #pragma unroll
                for (int mb = 0; mb < 4; ++mb) {
                    mma_bf16(acc[mb][2*cb],   A[mb][0], A[mb][1], A[mb][2], A[mb][3], b0, b1);
                    mma_bf16(acc[mb][2*cb+1], A[mb][0], A[mb][1], A[mb][2], A[mb][3], b2, b3);
                }
            }
        }
        // no trailing __syncthreads: next iteration's top barrier provides ordering
    }
}

__global__ __launch_bounds__(256, 2) void qkv_bf16_kernel() {
    extern __shared__ char smc[];
    uint32_t sb = smem_u32(smc);
    int tid = threadIdx.x, lane = tid & 31, w = tid >> 5;
    int wm = w & 1, wn = w >> 1;
    int g = lane >> 2, t = lane & 3;
    int b = blockIdx.z, o0 = blockIdx.y * 128, n0 = blockIdx.x * 128;
    const unsigned short* Abase = g_xh  + ((size_t)b * NPIX + n0) * CH;
    const unsigned short* Bbase = g_wbh + ((size_t)b * QKVC + o0) * CH;

    float acc[4][4][4];
    #pragma unroll
    for (int mb = 0; mb < 4; ++mb)
        #pragma unroll
        for (int nb = 0; nb < 4; ++nb)
            #pragma unroll
            for (int i = 0; i < 4; ++i) acc[mb][nb][i] = 0.f;

    gemm_bf16_core(sb, Abase, Bbase, acc, tid);

    int otile = blockIdx.y;
    if (otile < 4) {
        float fold = (otile < 2) ? QK_FOLD : 1.0f;
        unsigned short* dst = ((otile < 2) ? g_q : g_k) + (size_t)b * NPIX * CH;
        int obase = (otile < 2) ? o0 : (o0 - 256);
        #pragma unroll
        for (int nb = 0; nb < 4; ++nb) {
            int oo = o0 + wn*32 + nb*8 + 2*t;
            float2 bias = *(const float2*)&g_bb[b * QKVC + oo];
            int ol = obase + wn*32 + nb*8 + 2*t;
            #pragma unroll
            for (int mb = 0; mb < 4; ++mb) {
                int nr = n0 + wm*64 + mb*16 + g;
                __nv_bfloat162 h0 = __floats2bfloat162_rn((acc[mb][nb][0] + bias.x) * fold,
                                                          (acc[mb][nb][1] + bias.y) * fold);
                __nv_bfloat162 h1 = __floats2bfloat162_rn((acc[mb][nb][2] + bias.x) * fold,
                                                          (acc[mb][nb][3] + bias.y) * fold);
                *(__nv_bfloat162*)(dst + (size_t)nr * CH + ol)       = h0;
                *(__nv_bfloat162*)(dst + (size_t)(nr + 8) * CH + ol) = h1;
            }
        }
    } else {
        unsigned short* dst = g_v + (size_t)b * CH * NPIX;
        #pragma unroll
        for (int nb = 0; nb < 4; ++nb) {
            int oo = o0 + wn*32 + nb*8 + 2*t;
            float2 bias = *(const float2*)&g_bb[b * QKVC + oo];
            int cc = (o0 - 512) + wn*32 + nb*8 + 2*t;
            #pragma unroll
            for (int mb = 0; mb < 4; ++mb) {
                int nr = n0 + wm*64 + mb*16 + g;
                __half v0 = __float2half_rn(acc[mb][nb][0] + bias.x);
                __half v1 = __float2half_rn(acc[mb][nb][1] + bias.y);
                __half v2 = __float2half_rn(acc[mb][nb][2] + bias.x);
                __half v3 = __float2half_rn(acc[mb][nb][3] + bias.y);
                dst[(size_t)cc * NPIX + nr]           = *(unsigned short*)&v0;
                dst[(size_t)(cc + 1) * NPIX + nr]     = *(unsigned short*)&v1;
                dst[(size_t)cc * NPIX + nr + 8]       = *(unsigned short*)&v2;
                dst[(size_t)(cc + 1) * NPIX + nr + 8] = *(unsigned short*)&v3;
            }
        }
    }
}

// ---------------- K3: flash attention (round-11 exact) ----------------
#define KS_OFF 65536
#define VS_OFF 131072
#define FL_SMEM 196608
#define OH_OFF 4096
#define OH_STR 528

__device__ __forceinline__ void issue_kv(uint32_t sb, const unsigned short* kg,
                                         const unsigned short* vg, int kb, int buf, int tid) {
    int k0 = kb * 64;
    uint32_t kbase = sb + KS_OFF + buf * 32768;
    uint32_t vbase = sb + VS_OFF + buf * 32768;
    #pragma unroll
    for (int it = 0; it < 8; ++it) {
        int t = it * 256 + tid;
        int r = t >> 5, ch = t & 31;
        CP_ASYNC(kbase + r*512 + ((ch ^ (r & 7)) << 4),
                 kg + (size_t)(k0 + r) * CH + ch * 8);
    }
    #pragma unroll
    for (int it = 0; it < 8; ++it) {
        int t = it * 256 + tid;
        int r = t >> 3, ch = t & 7;
        CP_ASYNC(vbase + r*128 + ((ch ^ (r & 7)) << 4),
                 vg + (size_t)r * NPIX + k0 + ch * 8);
    }
}

__global__ __launch_bounds__(256, 1) void flash_mma_kernel() {
    extern __shared__ char sm[];
    uint32_t sb = smem_u32(sm);
    int tid = threadIdx.x, w = tid >> 5, l = tid & 31;
    int wr = w & 3, wh = w >> 2;
    int b = blockIdx.y, q0 = blockIdx.x * 128;
    const unsigned short* qg = g_q + (size_t)b * NPIX * CH;
    const unsigned short* kg = g_k + (size_t)b * NPIX * CH;
    const unsigned short* vg = g_v + (size_t)b * CH * NPIX;

    #pragma unroll
    for (int it = 0; it < 16; ++it) {
        int t = it * 256 + tid;
        int r = t >> 5, ch = t & 31;
        uint4 val = *(const uint4*)(qg + (size_t)(q0 + r) * CH + ch * 8);
        *(uint4*)(sm + r*512 + ((ch ^ (r & 7)) << 4)) = val;
    }
    issue_kv(sb, kg, vg, 0, 0, tid);
    CP_COMMIT();

    uint32_t oacc[2][32][2];
    #pragma unroll
    for (int mi = 0; mi < 2; ++mi)
        #pragma unroll
        for (int c = 0; c < 32; ++c) { oacc[mi][c][0] = 0u; oacc[mi][c][1] = 0u; }
    float lsum[2][2] = {{0.f, 0.f}, {0.f, 0.f}};

    int lg = l >> 2, lt = l & 3;
    int a_lrow = l & 15, a_lch = l >> 4;
    int b_roff = (l & 7) + ((l & 16) >> 1);
    int b_choff = (l >> 3) & 1;

    for (int kb = 0; kb < 64; ++kb) {
        CP_WAIT0();
        __syncthreads();
        if (kb < 63) { issue_kv(sb, kg, vg, kb + 1, (kb + 1) & 1, tid); CP_COMMIT(); }
        uint32_t kbase = sb + KS_OFF + (kb & 1) * 32768;
        uint32_t vbase = sb + VS_OFF + (kb & 1) * 32768;

        float sacc[2][4][4];
        #pragma unroll
        for (int mi = 0; mi < 2; ++mi)
            #pragma unroll
            for (int j = 0; j < 4; ++j)
                #pragma unroll
                for (int i = 0; i < 4; ++i) sacc[mi][j][i] = 0.f;

        #pragma unroll
        for (int kk = 0; kk < 16; ++kk) {
            uint32_t A[2][4];
            #pragma unroll
            for (int mi = 0; mi < 2; ++mi) {
                int qrow = 32*wr + 16*mi + a_lrow;
                ldsm4(A[mi][0], A[mi][1], A[mi][2], A[mi][3],
                      sb + qrow*512 + (((2*kk + a_lch) ^ (qrow & 7)) << 4));
            }
            #pragma unroll
            for (int cb = 0; cb < 2; ++cb) {
                int krow = 32*wh + 16*cb + b_roff;
                uint32_t b0, b1, b2, b3;
                ldsm4(b0, b1, b2, b3,
                      kbase + krow*512 + (((2*kk + b_choff) ^ (krow & 7)) << 4));
                #pragma unroll
                for (int mi = 0; mi < 2; ++mi) {
                    mma_bf16(sacc[mi][2*cb],   A[mi][0], A[mi][1], A[mi][2], A[mi][3], b0, b1);
                    mma_bf16(sacc[mi][2*cb+1], A[mi][0], A[mi][1], A[mi][2], A[mi][3], b2, b3);
                }
            }
        }

        uint32_t pf[2][4][2];
        #pragma unroll
        for (int mi = 0; mi < 2; ++mi) {
            #pragma unroll
            for (int ni = 0; ni < 4; ++ni) {
                float e0 = ex2f(sacc[mi][ni][0]), e1 = ex2f(sacc[mi][ni][1]);
                float e2 = ex2f(sacc[mi][ni][2]), e3 = ex2f(sacc[mi][ni][3]);
                lsum[mi][0] += e0 + e1;
                lsum[mi][1] += e2 + e3;
                __half2 h0 = __floats2half2_rn(e0, e1);
                __half2 h1 = __floats2half2_rn(e2, e3);
                pf[mi][ni][0] = *(uint32_t*)&h0;
                pf[mi][ni][1] = *(uint32_t*)&h1;
            }
        }

        #pragma unroll
        for (int j2 = 0; j2 < 2; ++j2) {
            int c2 = 2*(2*wh + j2) + b_choff;
            #pragma unroll
            for (int nb = 0; nb < 16; ++nb) {
                int vrow = 16*nb + b_roff;
                uint32_t b0, b1, b2, b3;
                ldsm4(b0, b1, b2, b3,
                      vbase + vrow*128 + ((c2 ^ (vrow & 7)) << 4));
                #pragma unroll
                for (int mi = 0; mi < 2; ++mi) {
                    mma_f16acc(oacc[mi][2*nb],
                               pf[mi][2*j2][0], pf[mi][2*j2][1],
                               pf[mi][2*j2+1][0], pf[mi][2*j2+1][1], b0, b1);
                    mma_f16acc(oacc[mi][2*nb+1],
                               pf[mi][2*j2][0], pf[mi][2*j2][1],
                               pf[mi][2*j2+1][0], pf[mi][2*j2+1][1], b2, b3);
                }
            }
        }
    }
    __syncthreads();

    float* LS = (float*)sm;
    #pragma unroll
    for (int mi = 0; mi < 2; ++mi)
        #pragma unroll
        for (int rr = 0; rr < 2; ++rr) {
            float v = lsum[mi][rr];
            v += __shfl_xor_sync(0xffffffffu, v, 1);
            v += __shfl_xor_sync(0xffffffffu, v, 2);
            LS[(32*wr + 16*mi + lg + 8*rr)*2 + wh] = v;
        }
    if (wh == 1) {
        #pragma unroll
        for (int mi = 0; mi < 2; ++mi) {
            int r0 = 32*wr + 16*mi + lg;
            #pragma unroll
            for (int c = 0; c < 32; ++c) {
                *(uint32_t*)(sm + OH_OFF + r0*OH_STR + (c*8 + 2*lt)*2)     = oacc[mi][c][0];
                *(uint32_t*)(sm + OH_OFF + (r0+8)*OH_STR + (c*8 + 2*lt)*2) = oacc[mi][c][1];
            }
        }
    }
    __syncthreads();

    if (wh == 0) {
        #pragma unroll
        for (int mi = 0; mi < 2; ++mi) {
            int lrow = 32*wr + 16*mi + lg;
            float li0 = 1.0f / (LS[lrow*2] + LS[lrow*2+1]);
            float li1 = 1.0f / (LS[(lrow+8)*2] + LS[(lrow+8)*2+1]);
            unsigned short* o0 = g_attnh + ((size_t)b * NPIX + q0 + lrow) * CH + 2*lt;
            unsigned short* o1 = o0 + 8 * CH;
            #pragma unroll
            for (int c = 0; c < 32; ++c) {
                uint32_t p0 = *(uint32_t*)(sm + OH_OFF + lrow*OH_STR + (c*8 + 2*lt)*2);
                uint32_t p1 = *(uint32_t*)(sm + OH_OFF + (lrow+8)*OH_STR + (c*8 + 2*lt)*2);
                float2 f0 = __half22float2(*(__half2*)&oacc[mi][c][0]);
                float2 g0 = __half22float2(*(__half2*)&p0);
                float2 f1 = __half22float2(*(__half2*)&oacc[mi][c][1]);
                float2 g1 = __half22float2(*(__half2*)&p1);
                __nv_bfloat162 h0 = __floats2bfloat162_rn((f0.x + g0.x) * li0, (f0.y + g0.y) * li0);
                __nv_bfloat162 h1 = __floats2bfloat162_rn((f1.x + g1.x) * li1, (f1.y + g1.y) * li1);
                *(uint32_t*)(o0 + c*8) = *(uint32_t*)&h0;
                *(uint32_t*)(o1 + c*8) = *(uint32_t*)&h1;
            }
        }
    }
}

// ---------------- K4: proj GEMM (bf16 mma) + residual ----------------
__global__ __launch_bounds__(256, 2) void proj_bf16_kernel(const float* __restrict__ x,
                                                           const float* __restrict__ b_proj,
                                                           float* __restrict__ out) {
    extern __shared__ char smc[];
    uint32_t sb = smem_u32(smc);
    int tid = threadIdx.x, lane = tid & 31, w = tid >> 5;
    int wm = w & 1, wn = w >> 1;
    int g = lane >> 2, t = lane & 3;
    int b = blockIdx.z, o0 = blockIdx.y * 128, n0 = blockIdx.x * 128;
    const unsigned short* Abase = g_attnh + ((size_t)b * NPIX + n0) * CH;
    const unsigned short* Bbase = g_wph + (size_t)o0 * CH;

    float acc[4][4][4];
    #pragma unroll
    for (int mb = 0; mb < 4; ++mb)
        #pragma unroll
        for (int nb = 0; nb < 4; ++nb)
            #pragma unroll
            for (int i = 0; i < 4; ++i) acc[mb][nb][i] = 0.f;

    gemm_bf16_core(sb, Abase, Bbase, acc, tid);

    #pragma unroll
    for (int nb = 0; nb < 4; ++nb) {
        int oo = o0 + wn*32 + nb*8 + 2*t;
        float2 bias = *(const float2*)&b_proj[oo];
        #pragma unroll
        for (int mb = 0; mb < 4; ++mb) {
            int nr = n0 + wm*64 + mb*16 + g;
            size_t i0 = ((size_t)b * CH + oo) * NPIX + nr;
            size_t i1 = i0 + NPIX;
            out[i0]     = x[i0]     + bias.x + acc[mb][nb][0];
            out[i1]     = x[i1]     + bias.y + acc[mb][nb][1];
            out[i0 + 8] = x[i0 + 8] + bias.x + acc[mb][nb][2];
            out[i1 + 8] = x[i1 + 8] + bias.y + acc[mb][nb][3];
        }
    }
}

// ---------------- launch ----------------
extern "C" void kernel_launch(void* const* d_in, const int* in_sizes, int n_in,
                              void* d_out, int out_size) {
    const float* x      = (const float*)d_in[0];
    const float* gamma  = (const float*)d_in[1];
    const float* beta   = (const float*)d_in[2];
    const float* w_qkv  = (const float*)d_in[3];
    const float* b_qkv  = (const float*)d_in[4];
    const float* w_proj = (const float*)d_in[5];
    const float* b_proj = (const float*)d_in[6];
    float* out = (float*)d_out;

    cudaFuncSetAttribute(flash_mma_kernel, cudaFuncAttributeMaxDynamicSharedMemorySize, FL_SMEM);
    cudaFuncSetAttribute(qkv_bf16_kernel, cudaFuncAttributeMaxDynamicSharedMemorySize, GB_SMEM);
    cudaFuncSetAttribute(proj_bf16_kernel, cudaFuncAttributeMaxDynamicSharedMemorySize, GB_SMEM);

    gn_part_kernel<<<256, 256>>>(x, w_proj);
    xpose_kernel<<<dim3(NPIX/64, CH/32, BATCH), 256>>>(x);
    build_wb_kernel<<<dim3(QKVC, BATCH), 256>>>(w_qkv, b_qkv, gamma, beta);
    qkv_bf16_kernel<<<dim3(NPIX/128, QKVC/128, BATCH), 256, GB_SMEM>>>();
    flash_mma_kernel<<<dim3(NPIX/128, BATCH), 256, FL_SMEM>>>();
    proj_bf16_kernel<<<dim3(NPIX/128, CH/128, BATCH), 256, GB_SMEM>>>(x, b_proj, out);
}

// round 16
// speedup vs baseline: 1.5193x; 1.0048x over previous
#include <cuda_runtime.h>
#include <cuda_bf16.h>
#include <cuda_fp16.h>
#include <math.h>
#include <stdint.h>

#define BATCH 8
#define CH    256
#define NPIX  4096
#define QKVC  768
#define GROUPS 8
#define CPG    32
#define EPS    1e-5f
#define QK_FOLD 0.0901687145f

// ---------------- scratch ----------------
__device__ __align__(16) unsigned short g_xh[BATCH * NPIX * CH];  // bf16 x^T [b][n][c]
__device__ __align__(16) unsigned short g_q[BATCH * NPIX * CH];   // bf16 [b][n][c], q*QK_FOLD
__device__ __align__(16) unsigned short g_k[BATCH * NPIX * CH];   // bf16 [b][n][c]
__device__ __align__(16) unsigned short g_v[BATCH * CH * NPIX];   // fp16 [b][c][n]
__device__ __align__(16) unsigned short g_attnh[BATCH * NPIX * CH]; // bf16 [b][n][c]
__device__ __align__(16) unsigned short g_wbh[BATCH * QKVC * CH]; // bf16 folded qkv weights
__device__ __align__(16) unsigned short g_wph[CH * CH];           // bf16 w_proj [o][c]
__device__ float g_bb  [BATCH * QKVC];
__device__ float g_part[BATCH * GROUPS * 8];   // 4 partials x (sum, sumsq) per (b,g)

// ================= helpers =================
__device__ __forceinline__ uint32_t smem_u32(const void* p) {
    uint32_t a;
    asm("{ .reg .u64 t; cvta.to.shared.u64 t, %1; cvt.u32.u64 %0, t; }" : "=r"(a) : "l"(p));
    return a;
}
__device__ __forceinline__ float ex2f(float x) {
    float r; asm("ex2.approx.f32 %0, %1;" : "=f"(r) : "f"(x)); return r;
}
__device__ __forceinline__ void ldsm4(uint32_t& r0, uint32_t& r1, uint32_t& r2, uint32_t& r3,
                                      uint32_t addr) {
    asm volatile("ldmatrix.sync.aligned.m8n8.x4.shared.b16 {%0,%1,%2,%3}, [%4];"
                 : "=r"(r0), "=r"(r1), "=r"(r2), "=r"(r3) : "r"(addr));
}
__device__ __forceinline__ void mma_bf16(float* d, uint32_t a0, uint32_t a1, uint32_t a2,
                                         uint32_t a3, uint32_t b0, uint32_t b1) {
    asm volatile("mma.sync.aligned.m16n8k16.row.col.f32.bf16.bf16.f32 "
                 "{%0,%1,%2,%3}, {%4,%5,%6,%7}, {%8,%9}, {%0,%1,%2,%3};"
                 : "+f"(d[0]), "+f"(d[1]), "+f"(d[2]), "+f"(d[3])
                 : "r"(a0), "r"(a1), "r"(a2), "r"(a3), "r"(b0), "r"(b1));
}
__device__ __forceinline__ void mma_f16acc(uint32_t* d, uint32_t a0, uint32_t a1, uint32_t a2,
                                           uint32_t a3, uint32_t b0, uint32_t b1) {
    asm volatile("mma.sync.aligned.m16n8k16.row.col.f16.f16.f16.f16 "
                 "{%0,%1}, {%2,%3,%4,%5}, {%6,%7}, {%0,%1};"
                 : "+r"(d[0]), "+r"(d[1])
                 : "r"(a0), "r"(a1), "r"(a2), "r"(a3), "r"(b0), "r"(b1));
}
#define CP_ASYNC(dst, src) \
    asm volatile("cp.async.cg.shared.global [%0], [%1], 16;" :: "r"(dst), "l"(src))
#define CP_COMMIT() asm volatile("cp.async.commit_group;" ::: "memory")
#define CP_WAIT0()  asm volatile("cp.async.wait_group 0;" ::: "memory")
#define CP_WAIT1()  asm volatile("cp.async.wait_group 1;" ::: "memory")

// ---------------- K0: groupnorm partial sums (+ w_proj conversion fold) ----------------
__global__ void gn_part_kernel(const float* __restrict__ x,
                               const float* __restrict__ w_proj) {
    int id = blockIdx.x;
    int b = id >> 5, g = (id >> 2) & 7, qtr = id & 3;
    if (id < 64) {
        int i = id * 256 + threadIdx.x;
        float4 v = ((const float4*)w_proj)[i];
        union { __nv_bfloat162 h[2]; uint2 u; } pk;
        pk.h[0] = __floats2bfloat162_rn(v.x, v.y);
        pk.h[1] = __floats2bfloat162_rn(v.z, v.w);
        ((uint2*)g_wph)[i] = pk.u;
    }
    const float4* xv = (const float4*)(x + ((size_t)b * CH + g * CPG) * NPIX) + qtr * 8192;
    float s = 0.f, s2 = 0.f;
    for (int i = threadIdx.x; i < 8192; i += 256) {
        float4 v = xv[i];
        s  += v.x + v.y + v.z + v.w;
        s2 += v.x*v.x + v.y*v.y + v.z*v.z + v.w*v.w;
    }
    __shared__ float rs[256], rs2[256];
    rs[threadIdx.x] = s; rs2[threadIdx.x] = s2;
    __syncthreads();
    for (int o = 128; o > 0; o >>= 1) {
        if (threadIdx.x < o) { rs[threadIdx.x] += rs[threadIdx.x+o]; rs2[threadIdx.x] += rs2[threadIdx.x+o]; }
        __syncthreads();
    }
    if (threadIdx.x == 0) {
        g_part[(b * 8 + g) * 8 + qtr * 2]     = rs[0];
        g_part[(b * 8 + g) * 8 + qtr * 2 + 1] = rs2[0];
    }
}

// ---------------- K0b: transpose x -> bf16 [b][n][c] ----------------
__global__ void xpose_kernel(const float* __restrict__ x) {
    __shared__ float ts[32][65];
    int b = blockIdx.z, c0 = blockIdx.y * 32, n0 = blockIdx.x * 64;
    const float* xb = x + ((size_t)b * CH + c0) * NPIX + n0;
    int tid = threadIdx.x;
    #pragma unroll
    for (int it = 0; it < 2; ++it) {
        int p = it * 256 + tid;
        int r = p >> 4, q = p & 15;
        float4 v = *(const float4*)(xb + (size_t)r * NPIX + q * 4);
        ts[r][q*4+0] = v.x; ts[r][q*4+1] = v.y; ts[r][q*4+2] = v.z; ts[r][q*4+3] = v.w;
    }
    __syncthreads();
    int nr = tid >> 2, cq = tid & 3;
    union { __nv_bfloat162 h[4]; uint4 u; } pk;
    #pragma unroll
    for (int j = 0; j < 4; ++j)
        pk.h[j] = __floats2bfloat162_rn(ts[cq*8 + 2*j][nr], ts[cq*8 + 2*j + 1][nr]);
    *(uint4*)(g_xh + ((size_t)b * NPIX + n0 + nr) * CH + c0 + cq * 8) = pk.u;
}

// ---------------- K1: stats finalize + fold affine into qkv weights ----------------
__global__ void build_wb_kernel(const float* __restrict__ w_qkv,
                                const float* __restrict__ b_qkv,
                                const float* __restrict__ gamma,
                                const float* __restrict__ beta) {
    int o = blockIdx.x, b = blockIdx.y, c = threadIdx.x;
    int g = c >> 5;
    const float* pp = g_part + (b * 8 + g) * 8;
    float s  = (pp[0] + pp[2]) + (pp[4] + pp[6]);
    float s2 = (pp[1] + pp[3]) + (pp[5] + pp[7]);
    float mean = s  * (1.0f / 131072.0f);
    float var  = s2 * (1.0f / 131072.0f) - mean * mean;
    float rinv = rsqrtf(var + EPS);
    float sc = rinv * gamma[c];
    float tt = beta[c] - mean * sc;
    float w = w_qkv[o * CH + c];
    __nv_bfloat16 wh = __float2bfloat16(w * sc);
    g_wbh[((size_t)b * QKVC + o) * CH + c] = *(unsigned short*)&wh;
    __shared__ float red[256];
    red[c] = w * tt;
    __syncthreads();
    for (int off = 128; off > 0; off >>= 1) {
        if (c < off) red[c] += red[c + off];
        __syncthreads();
    }
    if (c == 0) g_bb[b * QKVC + o] = b_qkv[o] + red[0];
}

// ---------------- K2: QKV GEMM (bf16 mma), 3-stage pipeline ----------------
#define GB_SMEM 98304   // A 3x16KB @0, B 3x16KB @49152

__device__ __forceinline__ void gemm_issue(uint32_t sb, const unsigned short* Abase,
                                           const unsigned short* Bbase, int s, int tid) {
    int buf = s % 3, c0 = s * 64;
    uint32_t adst = sb + buf * 16384;
    uint32_t bdst = sb + 49152 + buf * 16384;
    #pragma unroll
    for (int it = 0; it < 4; ++it) {
        int t = it * 256 + tid;
        int r = t >> 3, ch = t & 7;
        CP_ASYNC(adst + r*128 + ((ch ^ (r & 7)) << 4), Abase + (size_t)r * CH + c0 + ch * 8);
    }
    #pragma unroll
    for (int it = 0; it < 4; ++it) {
        int t = it * 256 + tid;
        int r = t >> 3, ch = t & 7;
        CP_ASYNC(bdst + r*128 + ((ch ^ (r & 7)) << 4), Bbase + (size_t)r * CH + c0 + ch * 8);
    }
}

__device__ __forceinline__ void gemm_bf16_core(uint32_t sb, const unsigned short* Abase,
                                               const unsigned short* Bbase,
                                               float acc[4][4][4], int tid) {
    int l = tid & 31, w = tid >> 5;
    int wm = w & 1, wn = w >> 1;
    int a_lrow = l & 15, a_lch = l >> 4;
    int b_roff = (l & 7) + ((l & 16) >> 1);
    int b_choff = (l >> 3) & 1;

    gemm_issue(sb, Abase, Bbase, 0, tid); CP_COMMIT();
    gemm_issue(sb, Abase, Bbase, 1, tid); CP_COMMIT();
    for (int s = 0; s < 4; ++s) {
        if (s < 3) CP_WAIT1(); else CP_WAIT0();   // group s complete
        __syncthreads();
        if (s < 2) { gemm_issue(sb, Abase, Bbase, s + 2, tid); CP_COMMIT(); }
        uint32_t abuf = sb + (s % 3) * 16384;
        uint32_t bbuf = sb + 49152 + (s % 3) * 16384;
        #pragma unroll
        for (int kk = 0; kk < 4; ++kk) {
            uint32_t A[4][4];
            #pragma unroll
            for (int mb = 0; mb < 4; ++mb) {
                int row = wm*64 + mb*16 + a_lrow;
                ldsm4(A[mb][0], A[mb][1], A[mb][2], A[mb][3],
                      abuf + row*128 + (((2*kk + a_lch) ^ (row & 7)) << 4));
            }
            #pragma unroll
            for (int cb = 0; cb < 2; ++cb) {
                int row = wn*32 + cb*16 + b_roff;
                uint32_t b0, b1, b2, b3;
                ldsm4(b0, b1, b2, b3,
                      bbuf + row*128 + (((2*kk + b_choff) ^ (row & 7)) << 4));
                #pragma unroll
                for (int mb = 0; mb < 4; ++mb) {
                    mma_bf16(acc[mb][2*cb],   A[mb][0], A[mb][1], A[mb][2], A[mb][3], b0, b1);
                    mma_bf16(acc[mb][2*cb+1], A[mb][0], A[mb][1], A[mb][2], A[mb][3], b2, b3);
                }
            }
        }
        // next iteration's top barrier orders buffer reuse
    }
}

__global__ __launch_bounds__(256, 2) void qkv_bf16_kernel() {
    extern __shared__ char smc[];
    uint32_t sb = smem_u32(smc);
    int tid = threadIdx.x, lane = tid & 31, w = tid >> 5;
    int wm = w & 1, wn = w >> 1;
    int g = lane >> 2, t = lane & 3;
    int b = blockIdx.z, o0 = blockIdx.y * 128, n0 = blockIdx.x * 128;
    const unsigned short* Abase = g_xh  + ((size_t)b * NPIX + n0) * CH;
    const unsigned short* Bbase = g_wbh + ((size_t)b * QKVC + o0) * CH;

    float acc[4][4][4];
    #pragma unroll
    for (int mb = 0; mb < 4; ++mb)
        #pragma unroll
        for (int nb = 0; nb < 4; ++nb)
            #pragma unroll
            for (int i = 0; i < 4; ++i) acc[mb][nb][i] = 0.f;

    gemm_bf16_core(sb, Abase, Bbase, acc, tid);

    int otile = blockIdx.y;
    if (otile < 4) {
        float fold = (otile < 2) ? QK_FOLD : 1.0f;
        unsigned short* dst = ((otile < 2) ? g_q : g_k) + (size_t)b * NPIX * CH;
        int obase = (otile < 2) ? o0 : (o0 - 256);
        #pragma unroll
        for (int nb = 0; nb < 4; ++nb) {
            int oo = o0 + wn*32 + nb*8 + 2*t;
            float2 bias = *(const float2*)&g_bb[b * QKVC + oo];
            int ol = obase + wn*32 + nb*8 + 2*t;
            #pragma unroll
            for (int mb = 0; mb < 4; ++mb) {
                int nr = n0 + wm*64 + mb*16 + g;
                __nv_bfloat162 h0 = __floats2bfloat162_rn((acc[mb][nb][0] + bias.x) * fold,
                                                          (acc[mb][nb][1] + bias.y) * fold);
                __nv_bfloat162 h1 = __floats2bfloat162_rn((acc[mb][nb][2] + bias.x) * fold,
                                                          (acc[mb][nb][3] + bias.y) * fold);
                *(__nv_bfloat162*)(dst + (size_t)nr * CH + ol)       = h0;
                *(__nv_bfloat162*)(dst + (size_t)(nr + 8) * CH + ol) = h1;
            }
        }
    } else {
        unsigned short* dst = g_v + (size_t)b * CH * NPIX;
        #pragma unroll
        for (int nb = 0; nb < 4; ++nb) {
            int oo = o0 + wn*32 + nb*8 + 2*t;
            float2 bias = *(const float2*)&g_bb[b * QKVC + oo];
            int cc = (o0 - 512) + wn*32 + nb*8 + 2*t;
            #pragma unroll
            for (int mb = 0; mb < 4; ++mb) {
                int nr = n0 + wm*64 + mb*16 + g;
                __half v0 = __float2half_rn(acc[mb][nb][0] + bias.x);
                __half v1 = __float2half_rn(acc[mb][nb][1] + bias.y);
                __half v2 = __float2half_rn(acc[mb][nb][2] + bias.x);
                __half v3 = __float2half_rn(acc[mb][nb][3] + bias.y);
                dst[(size_t)cc * NPIX + nr]           = *(unsigned short*)&v0;
                dst[(size_t)(cc + 1) * NPIX + nr]     = *(unsigned short*)&v1;
                dst[(size_t)cc * NPIX + nr + 8]       = *(unsigned short*)&v2;
                dst[(size_t)(cc + 1) * NPIX + nr + 8] = *(unsigned short*)&v3;
            }
        }
    }
}

// ---------------- K3: flash attention (round-11 exact) ----------------
#define KS_OFF 65536
#define VS_OFF 131072
#define FL_SMEM 196608
#define OH_OFF 4096
#define OH_STR 528

__device__ __forceinline__ void issue_kv(uint32_t sb, const unsigned short* kg,
                                         const unsigned short* vg, int kb, int buf, int tid) {
    int k0 = kb * 64;
    uint32_t kbase = sb + KS_OFF + buf * 32768;
    uint32_t vbase = sb + VS_OFF + buf * 32768;
    #pragma unroll
    for (int it = 0; it < 8; ++it) {
        int t = it * 256 + tid;
        int r = t >> 5, ch = t & 31;
        CP_ASYNC(kbase + r*512 + ((ch ^ (r & 7)) << 4),
                 kg + (size_t)(k0 + r) * CH + ch * 8);
    }
    #pragma unroll
    for (int it = 0; it < 8; ++it) {
        int t = it * 256 + tid;
        int r = t >> 3, ch = t & 7;
        CP_ASYNC(vbase + r*128 + ((ch ^ (r & 7)) << 4),
                 vg + (size_t)r * NPIX + k0 + ch * 8);
    }
}

__global__ __launch_bounds__(256, 1) void flash_mma_kernel() {
    extern __shared__ char sm[];
    uint32_t sb = smem_u32(sm);
    int tid = threadIdx.x, w = tid >> 5, l = tid & 31;
    int wr = w & 3, wh = w >> 2;
    int b = blockIdx.y, q0 = blockIdx.x * 128;
    const unsigned short* qg = g_q + (size_t)b * NPIX * CH;
    const unsigned short* kg = g_k + (size_t)b * NPIX * CH;
    const unsigned short* vg = g_v + (size_t)b * CH * NPIX;

    #pragma unroll
    for (int it = 0; it < 16; ++it) {
        int t = it * 256 + tid;
        int r = t >> 5, ch = t & 31;
        uint4 val = *(const uint4*)(qg + (size_t)(q0 + r) * CH + ch * 8);
        *(uint4*)(sm + r*512 + ((ch ^ (r & 7)) << 4)) = val;
    }
    issue_kv(sb, kg, vg, 0, 0, tid);
    CP_COMMIT();

    uint32_t oacc[2][32][2];
    #pragma unroll
    for (int mi = 0; mi < 2; ++mi)
        #pragma unroll
        for (int c = 0; c < 32; ++c) { oacc[mi][c][0] = 0u; oacc[mi][c][1] = 0u; }
    float lsum[2][2] = {{0.f, 0.f}, {0.f, 0.f}};

    int lg = l >> 2, lt = l & 3;
    int a_lrow = l & 15, a_lch = l >> 4;
    int b_roff = (l & 7) + ((l & 16) >> 1);
    int b_choff = (l >> 3) & 1;

    for (int kb = 0; kb < 64; ++kb) {
        CP_WAIT0();
        __syncthreads();
        if (kb < 63) { issue_kv(sb, kg, vg, kb + 1, (kb + 1) & 1, tid); CP_COMMIT(); }
        uint32_t kbase = sb + KS_OFF + (kb & 1) * 32768;
        uint32_t vbase = sb + VS_OFF + (kb & 1) * 32768;

        float sacc[2][4][4];
        #pragma unroll
        for (int mi = 0; mi < 2; ++mi)
            #pragma unroll
            for (int j = 0; j < 4; ++j)
                #pragma unroll
                for (int i = 0; i < 4; ++i) sacc[mi][j][i] = 0.f;

        #pragma unroll
        for (int kk = 0; kk < 16; ++kk) {
            uint32_t A[2][4];
            #pragma unroll
            for (int mi = 0; mi < 2; ++mi) {
                int qrow = 32*wr + 16*mi + a_lrow;
                ldsm4(A[mi][0], A[mi][1], A[mi][2], A[mi][3],
                      sb + qrow*512 + (((2*kk + a_lch) ^ (qrow & 7)) << 4));
            }
            #pragma unroll
            for (int cb = 0; cb < 2; ++cb) {
                int krow = 32*wh + 16*cb + b_roff;
                uint32_t b0, b1, b2, b3;
                ldsm4(b0, b1, b2, b3,
                      kbase + krow*512 + (((2*kk + b_choff) ^ (krow & 7)) << 4));
                #pragma unroll
                for (int mi = 0; mi < 2; ++mi) {
                    mma_bf16(sacc[mi][2*cb],   A[mi][0], A[mi][1], A[mi][2], A[mi][3], b0, b1);
                    mma_bf16(sacc[mi][2*cb+1], A[mi][0], A[mi][1], A[mi][2], A[mi][3], b2, b3);
                }
            }
        }

        uint32_t pf[2][4][2];
        #pragma unroll
        for (int mi = 0; mi < 2; ++mi) {
            #pragma unroll
            for (int ni = 0; ni < 4; ++ni) {
                float e0 = ex2f(sacc[mi][ni][0]), e1 = ex2f(sacc[mi][ni][1]);
                float e2 = ex2f(sacc[mi][ni][2]), e3 = ex2f(sacc[mi][ni][3]);
                lsum[mi][0] += e0 + e1;
                lsum[mi][1] += e2 + e3;
                __half2 h0 = __floats2half2_rn(e0, e1);
                __half2 h1 = __floats2half2_rn(e2, e3);
                pf[mi][ni][0] = *(uint32_t*)&h0;
                pf[mi][ni][1] = *(uint32_t*)&h1;
            }
        }

        #pragma unroll
        for (int j2 = 0; j2 < 2; ++j2) {
            int c2 = 2*(2*wh + j2) + b_choff;
            #pragma unroll
            for (int nb = 0; nb < 16; ++nb) {
                int vrow = 16*nb + b_roff;
                uint32_t b0, b1, b2, b3;
                ldsm4(b0, b1, b2, b3,
                      vbase + vrow*128 + ((c2 ^ (vrow & 7)) << 4));
                #pragma unroll
                for (int mi = 0; mi < 2; ++mi) {
                    mma_f16acc(oacc[mi][2*nb],
                               pf[mi][2*j2][0], pf[mi][2*j2][1],
                               pf[mi][2*j2+1][0], pf[mi][2*j2+1][1], b0, b1);
                    mma_f16acc(oacc[mi][2*nb+1],
                               pf[mi][2*j2][0], pf[mi][2*j2][1],
                               pf[mi][2*j2+1][0], pf[mi][2*j2+1][1], b2, b3);
                }
            }
        }
    }
    __syncthreads();

    float* LS = (float*)sm;
    #pragma unroll
    for (int mi = 0; mi < 2; ++mi)
        #pragma unroll
        for (int rr = 0; rr < 2; ++rr) {
            float v = lsum[mi][rr];
            v += __shfl_xor_sync(0xffffffffu, v, 1);
            v += __shfl_xor_sync(0xffffffffu, v, 2);
            LS[(32*wr + 16*mi + lg + 8*rr)*2 + wh] = v;
        }
    if (wh == 1) {
        #pragma unroll
        for (int mi = 0; mi < 2; ++mi) {
            int r0 = 32*wr + 16*mi + lg;
            #pragma unroll
            for (int c = 0; c < 32; ++c) {
                *(uint32_t*)(sm + OH_OFF + r0*OH_STR + (c*8 + 2*lt)*2)     = oacc[mi][c][0];
                *(uint32_t*)(sm + OH_OFF + (r0+8)*OH_STR + (c*8 + 2*lt)*2) = oacc[mi][c][1];
            }
        }
    }
    __syncthreads();

    if (wh == 0) {
        #pragma unroll
        for (int mi = 0; mi < 2; ++mi) {
            int lrow = 32*wr + 16*mi + lg;
            float li0 = 1.0f / (LS[lrow*2] + LS[lrow*2+1]);
            float li1 = 1.0f / (LS[(lrow+8)*2] + LS[(lrow+8)*2+1]);
            unsigned short* o0 = g_attnh + ((size_t)b * NPIX + q0 + lrow) * CH + 2*lt;
            unsigned short* o1 = o0 + 8 * CH;
            #pragma unroll
            for (int c = 0; c < 32; ++c) {
                uint32_t p0 = *(uint32_t*)(sm + OH_OFF + lrow*OH_STR + (c*8 + 2*lt)*2);
                uint32_t p1 = *(uint32_t*)(sm + OH_OFF + (lrow+8)*OH_STR + (c*8 + 2*lt)*2);
                float2 f0 = __half22float2(*(__half2*)&oacc[mi][c][0]);
                float2 g0 = __half22float2(*(__half2*)&p0);
                float2 f1 = __half22float2(*(__half2*)&oacc[mi][c][1]);
                float2 g1 = __half22float2(*(__half2*)&p1);
                __nv_bfloat162 h0 = __floats2bfloat162_rn((f0.x + g0.x) * li0, (f0.y + g0.y) * li0);
                __nv_bfloat162 h1 = __floats2bfloat162_rn((f1.x + g1.x) * li1, (f1.y + g1.y) * li1);
                *(uint32_t*)(o0 + c*8) = *(uint32_t*)&h0;
                *(uint32_t*)(o1 + c*8) = *(uint32_t*)&h1;
            }
        }
    }
}

// ---------------- K4: proj GEMM (bf16 mma) + residual ----------------
__global__ __launch_bounds__(256, 2) void proj_bf16_kernel(const float* __restrict__ x,
                                                           const float* __restrict__ b_proj,
                                                           float* __restrict__ out) {
    extern __shared__ char smc[];
    uint32_t sb = smem_u32(smc);
    int tid = threadIdx.x, lane = tid & 31, w = tid >> 5;
    int wm = w & 1, wn = w >> 1;
    int g = lane >> 2, t = lane & 3;
    int b = blockIdx.z, o0 = blockIdx.y * 128, n0 = blockIdx.x * 128;
    const unsigned short* Abase = g_attnh + ((size_t)b * NPIX + n0) * CH;
    const unsigned short* Bbase = g_wph + (size_t)o0 * CH;

    float acc[4][4][4];
    #pragma unroll
    for (int mb = 0; mb < 4; ++mb)
        #pragma unroll
        for (int nb = 0; nb < 4; ++nb)
            #pragma unroll
            for (int i = 0; i < 4; ++i) acc[mb][nb][i] = 0.f;

    gemm_bf16_core(sb, Abase, Bbase, acc, tid);

    #pragma unroll
    for (int nb = 0; nb < 4; ++nb) {
        int oo = o0 + wn*32 + nb*8 + 2*t;
        float2 bias = *(const float2*)&b_proj[oo];
        #pragma unroll
        for (int mb = 0; mb < 4; ++mb) {
            int nr = n0 + wm*64 + mb*16 + g;
            size_t i0 = ((size_t)b * CH + oo) * NPIX + nr;
            size_t i1 = i0 + NPIX;
            out[i0]     = x[i0]     + bias.x + acc[mb][nb][0];
            out[i1]     = x[i1]     + bias.y + acc[mb][nb][1];
            out[i0 + 8] = x[i0 + 8] + bias.x + acc[mb][nb][2];
            out[i1 + 8] = x[i1 + 8] + bias.y + acc[mb][nb][3];
        }
    }
}

// ---------------- launch ----------------
extern "C" void kernel_launch(void* const* d_in, const int* in_sizes, int n_in,
                              void* d_out, int out_size) {
    const float* x      = (const float*)d_in[0];
    const float* gamma  = (const float*)d_in[1];
    const float* beta   = (const float*)d_in[2];
    const float* w_qkv  = (const float*)d_in[3];
    const float* b_qkv  = (const float*)d_in[4];
    const float* w_proj = (const float*)d_in[5];
    const float* b_proj = (const float*)d_in[6];
    float* out = (float*)d_out;

    cudaFuncSetAttribute(flash_mma_kernel, cudaFuncAttributeMaxDynamicSharedMemorySize, FL_SMEM);
    cudaFuncSetAttribute(qkv_bf16_kernel, cudaFuncAttributeMaxDynamicSharedMemorySize, GB_SMEM);
    cudaFuncSetAttribute(proj_bf16_kernel, cudaFuncAttributeMaxDynamicSharedMemorySize, GB_SMEM);

    gn_part_kernel<<<256, 256>>>(x, w_proj);
    xpose_kernel<<<dim3(NPIX/64, CH/32, BATCH), 256>>>(x);
    build_wb_kernel<<<dim3(QKVC, BATCH), 256>>>(w_qkv, b_qkv, gamma, beta);
    qkv_bf16_kernel<<<dim3(NPIX/128, QKVC/128, BATCH), 256, GB_SMEM>>>();
    flash_mma_kernel<<<dim3(NPIX/128, BATCH), 256, FL_SMEM>>>();
    proj_bf16_kernel<<<dim3(NPIX/128, CH/128, BATCH), 256, GB_SMEM>>>(x, b_proj, out);
}